// round 7
// baseline (speedup 1.0000x reference)
#include <cuda_runtime.h>
#include <cuda_fp16.h>

#define Bx     2
#define Hx     512
#define Wx     1024
#define HWx    (Hx * Wx)          // 524288
#define NSEG   16
#define NBINS  32768
#define BIN_SCALE 16384.0f
#define MINPIX 128.0f
#define BPB    256                // blocks per batch for pass3

// ---- globals ----
__device__ __align__(16) unsigned long long g_hist[NSEG * NBINS]; // low=neg, high=pos
__device__ __align__(16) float g_acc[NSEG * 6];   // cnt, Se0, Se1, Ss0, Ss1, Q
__device__ __align__(16) float g_seed_bg[Bx];
__device__ __align__(16) float g_fg_s[NSEG];
__device__ __align__(16) float g_lov[NSEG];
__device__ __align__(16) float g_params[NSEG * 4]; // c0 c1 sx0 sx1
// scratch (not zeroed)
__device__ __align__(16) __half g_seeds[Bx * 8 * HWx];       // [b][c][hw]
__device__ __align__(16) unsigned g_mbits[Bx * HWx / 4];     // byte j: bit n = mask n

__device__ const float FGW[8] = {10.0f, 10.0f, 10.0f, 40.0f, 80.0f, 100.0f, 60.0f, 20.0f};

__device__ __forceinline__ float wred(float v) {
    v += __shfl_down_sync(0xffffffffu, v, 16);
    v += __shfl_down_sync(0xffffffffu, v, 8);
    v += __shfl_down_sync(0xffffffffu, v, 4);
    v += __shfl_down_sync(0xffffffffu, v, 2);
    v += __shfl_down_sync(0xffffffffu, v, 1);
    return v;
}

// 1-MUFU tanh; used identically in k_sums4 and k_pass3 (consistency matters)
__device__ __forceinline__ float tanh_approx(float x) {
    float r;
    asm("tanh.approx.f32 %0, %1;" : "=f"(r) : "f"(x));
    return r;
}
// sigmoid pair via one tanh.approx.f16x2:  s = 0.5 + 0.5*tanh(x/2)
__device__ __forceinline__ __half2 sigmoid2_h(float a, float b) {
    __half2 x = __floats2half2_rn(0.5f * a, 0.5f * b);
    __half2 t;
    asm("tanh.approx.f16x2 %0, %1;" : "=r"(*(unsigned*)&t) : "r"(*(unsigned*)&x));
    const __half2 half2_half = __floats2half2_rn(0.5f, 0.5f);
    return __hfma2(t, half2_half, half2_half);
}

// ---------------------------------------------------------------- zero
__global__ void k_zero() {
    size_t tid = blockIdx.x * blockDim.x + threadIdx.x;
    size_t stride = (size_t)gridDim.x * blockDim.x;
    float4* p = reinterpret_cast<float4*>(g_hist);
    for (size_t i = tid; i < sizeof(g_hist) / 16; i += stride)
        p[i] = make_float4(0.f, 0.f, 0.f, 0.f);
    if (blockIdx.x == 0 && threadIdx.x < 160) {
        int t = threadIdx.x;
        if (t < NSEG * 6) g_acc[t] = 0.f;
        if (t < Bx) g_seed_bg[t] = 0.f;
        if (t < NSEG) { g_fg_s[t] = 0.f; g_lov[t] = 0.f; }
    }
}

// ---------------------------------------------------------------- k_seed: ch4-11 + bbox (measured at HBM roofline)
__global__ void __launch_bounds__(256, 4) k_seed(const float* __restrict__ pred,
                                                 const int* __restrict__ bbox) {
    int b = blockIdx.x / BPB;
    int blk = blockIdx.x % BPB;
    const float* pb = pred + (size_t)b * 12 * HWx;
    const int* bbb = bbox + (size_t)b * 9 * HWx;
    __half* sdo = g_seeds + (size_t)b * 8 * HWx;

    float bg = 0.f;
    for (int g = blk * 256 + threadIdx.x; g < HWx / 4; g += BPB * 256) {
        int hw = g * 4;
#pragma unroll
        for (int c = 0; c < 8; c++) {
            float4 sv = *(const float4*)(pb + (size_t)(4 + c) * HWx + hw);
            int4 bv = *(const int4*)(bbb + (size_t)(1 + c) * HWx + hw);
            __half2 s01 = sigmoid2_h(sv.x, sv.y);
            __half2 s23 = sigmoid2_h(sv.z, sv.w);
            float2 f01 = __half22float2(s01);
            float2 f23 = __half22float2(s23);
            if (bv.x == 0) bg = fmaf(f01.x, f01.x, bg);
            if (bv.y == 0) bg = fmaf(f01.y, f01.y, bg);
            if (bv.z == 0) bg = fmaf(f23.x, f23.x, bg);
            if (bv.w == 0) bg = fmaf(f23.y, f23.y, bg);
            uint2 pk;
            pk.x = *reinterpret_cast<unsigned*>(&s01);
            pk.y = *reinterpret_cast<unsigned*>(&s23);
            *(uint2*)(sdo + (size_t)c * HWx + hw) = pk;
        }
    }
    bg = wred(bg);
    if ((threadIdx.x & 31) == 0) atomicAdd(&g_seed_bg[b], bg);
}

// ---------------------------------------------------------------- k_sums4: masks[n0..n0+3] + ch0-3
// one 4-pixel group per thread; 512 blocks per batch
__global__ void __launch_bounds__(256) k_sums4(const float* __restrict__ pred,
                                               const int* __restrict__ masks,
                                               int n0) {
    int b = blockIdx.x >> 9;            // / 512
    int blk = blockIdx.x & 511;
    const float* pb = pred + (size_t)b * 12 * HWx;
    const int* mb  = masks + ((size_t)b * 8 + n0) * HWx;
    unsigned* mbo = g_mbits + (size_t)b * HWx / 4;

    int g = blk * 256 + threadIdx.x;    // group index in [0, 131072)
    int hw = g * 4;
    int w = hw & (Wx - 1);
    int h = hw >> 10;
    float ybase = (float)h * (1.0f / 1023.0f);

    float4 p0 = *(const float4*)(pb + hw);
    float4 p1 = *(const float4*)(pb + HWx + hw);
    float4 s0v = *(const float4*)(pb + 2 * HWx + hw);
    float4 s1v = *(const float4*)(pb + 3 * HWx + hw);

    float e0[4], e1[4];
    e0[0] = tanh_approx(p0.x) + (float)(w + 0) * (2.0f / 2047.0f);
    e0[1] = tanh_approx(p0.y) + (float)(w + 1) * (2.0f / 2047.0f);
    e0[2] = tanh_approx(p0.z) + (float)(w + 2) * (2.0f / 2047.0f);
    e0[3] = tanh_approx(p0.w) + (float)(w + 3) * (2.0f / 2047.0f);
    e1[0] = tanh_approx(p1.x) + ybase;
    e1[1] = tanh_approx(p1.y) + ybase;
    e1[2] = tanh_approx(p1.z) + ybase;
    e1[3] = tanh_approx(p1.w) + ybase;
    float sg0[4] = {s0v.x, s0v.y, s0v.z, s0v.w};
    float sg1[4] = {s1v.x, s1v.y, s1v.z, s1v.w};
    float q4[4];
#pragma unroll
    for (int j = 0; j < 4; j++) q4[j] = fmaf(sg0[j], sg0[j], sg1[j] * sg1[j]);

    float c_[4]  = {0,0,0,0};
    float ae0[4] = {0,0,0,0};
    float ae1[4] = {0,0,0,0};
    float as0[4] = {0,0,0,0};
    float as1[4] = {0,0,0,0};
    float qq[4]  = {0,0,0,0};
    unsigned bits = 0;

#pragma unroll
    for (int n = 0; n < 4; n++) {
        int4 mv = *(const int4*)(mb + (size_t)n * HWx + hw);
        float mf[4];
        mf[0] = (mv.x > 0) ? 1.f : 0.f;
        mf[1] = (mv.y > 0) ? 1.f : 0.f;
        mf[2] = (mv.z > 0) ? 1.f : 0.f;
        mf[3] = (mv.w > 0) ? 1.f : 0.f;
#pragma unroll
        for (int j = 0; j < 4; j++) {
            c_[n] += mf[j];
            ae0[n] = fmaf(mf[j], e0[j], ae0[n]);
            ae1[n] = fmaf(mf[j], e1[j], ae1[n]);
            as0[n] = fmaf(mf[j], sg0[j], as0[n]);
            as1[n] = fmaf(mf[j], sg1[j], as1[n]);
            qq[n]  = fmaf(mf[j], q4[j], qq[n]);
            if (mf[j] != 0.f) bits |= (1u << (n0 + n + j * 8));
        }
    }
    // both halves OR their bits into the same word
    if (n0 == 0) mbo[g] = bits;
    else atomicOr(&mbo[g], bits);

#pragma unroll
    for (int n = 0; n < 4; n++) {
        int seg = b * 8 + n0 + n;
        float v;
        v = wred(c_[n]);  if ((threadIdx.x & 31) == 0) atomicAdd(&g_acc[seg * 6 + 0], v);
        v = wred(ae0[n]); if ((threadIdx.x & 31) == 0) atomicAdd(&g_acc[seg * 6 + 1], v);
        v = wred(ae1[n]); if ((threadIdx.x & 31) == 0) atomicAdd(&g_acc[seg * 6 + 2], v);
        v = wred(as0[n]); if ((threadIdx.x & 31) == 0) atomicAdd(&g_acc[seg * 6 + 3], v);
        v = wred(as1[n]); if ((threadIdx.x & 31) == 0) atomicAdd(&g_acc[seg * 6 + 4], v);
        v = wred(qq[n]);  if ((threadIdx.x & 31) == 0) atomicAdd(&g_acc[seg * 6 + 5], v);
    }
}

// ---------------------------------------------------------------- params
__global__ void k_params() {
    int t = threadIdx.x;
    if (t < NSEG) {
        float cnt = g_acc[t * 6 + 0];
        float cs = fmaxf(cnt, 1.f);
        float inv = 1.f / cs;
        g_params[t * 4 + 0] = g_acc[t * 6 + 1] * inv;
        g_params[t * 4 + 1] = g_acc[t * 6 + 2] * inv;
        g_params[t * 4 + 2] = expf(g_acc[t * 6 + 3] * inv * 10.f);
        g_params[t * 4 + 3] = expf(g_acc[t * 6 + 4] * inv * 10.f);
    }
}

// ---------------------------------------------------------------- pass3: dist, hist, seed_fg
__global__ void __launch_bounds__(256, 2) k_pass3(const float* __restrict__ pred,
                                                  const int* __restrict__ cls_ids) {
    int b = blockIdx.x / BPB;
    int blk = blockIdx.x % BPB;

    __shared__ float sp[8][4];
    __shared__ int sch[8];
    if (threadIdx.x < 32) {
        int n = threadIdx.x / 4, k = threadIdx.x % 4;
        sp[n][k] = g_params[(b * 8 + n) * 4 + k];
    }
    if (threadIdx.x < 8) sch[threadIdx.x] = cls_ids[b * 8 + threadIdx.x];
    __syncthreads();

    float c0[8], c1[8], sx0[8], sx1[8];
    const __half* sdp[8];
#pragma unroll
    for (int n = 0; n < 8; n++) {
        c0[n] = sp[n][0]; c1[n] = sp[n][1];
        sx0[n] = sp[n][2]; sx1[n] = sp[n][3];
        sdp[n] = g_seeds + ((size_t)b * 8 + sch[n]) * HWx;
    }
    float fa[8] = {0,0,0,0,0,0,0,0};

    const float* pb = pred + (size_t)b * 12 * HWx;
    const unsigned* mbi = g_mbits + (size_t)b * HWx / 4;
    unsigned long long* hb = &g_hist[(size_t)(b * 8) * NBINS];

    for (int g = blk * 256 + threadIdx.x; g < HWx / 4; g += BPB * 256) {
        int hw = g * 4;
        int w = hw & (Wx - 1);
        int h = hw >> 10;
        float ybase = (float)h * (1.0f / 1023.0f);
        float4 p0 = *(const float4*)(pb + hw);
        float4 p1 = *(const float4*)(pb + HWx + hw);
        float e0[4], e1[4];
        e0[0] = tanh_approx(p0.x) + (float)(w + 0) * (2.0f / 2047.0f);
        e0[1] = tanh_approx(p0.y) + (float)(w + 1) * (2.0f / 2047.0f);
        e0[2] = tanh_approx(p0.z) + (float)(w + 2) * (2.0f / 2047.0f);
        e0[3] = tanh_approx(p0.w) + (float)(w + 3) * (2.0f / 2047.0f);
        e1[0] = tanh_approx(p1.x) + ybase;
        e1[1] = tanh_approx(p1.y) + ybase;
        e1[2] = tanh_approx(p1.z) + ybase;
        e1[3] = tanh_approx(p1.w) + ybase;
        unsigned bits = mbi[g];

#pragma unroll
        for (int n = 0; n < 8; n++) {
            uint2 svp = *(const uint2*)(sdp[n] + hw);
            __half2 hA = *reinterpret_cast<__half2*>(&svp.x);
            __half2 hB = *reinterpret_cast<__half2*>(&svp.y);
            float2 fA = __half22float2(hA);
            float2 fB = __half22float2(hB);
            float sv[4] = {fA.x, fA.y, fB.x, fB.y};
#pragma unroll
            for (int j = 0; j < 4; j++) {
                int lab = (bits >> (n + j * 8)) & 1;
                float labf = (float)lab;
                float dx = e0[j] - c0[n];
                float dy = e1[j] - c1[n];
                float d2 = fmaf(dx * dx, sx0[n], dy * dy * sx1[n]);
                float dist = __expf(-d2);
                float eb = fabsf(dist - labf) * (2.0f * BIN_SCALE);
                int bin = min((int)eb, NBINS - 1);
                atomicAdd(&hb[(size_t)n * NBINS + bin],
                          lab ? (1ull << 32) : 1ull);
                float dd = sv[j] - dist;
                if (lab) fa[n] = fmaf(dd, dd, fa[n]);
            }
        }
    }
#pragma unroll
    for (int n = 0; n < 8; n++) {
        float v = wred(fa[n]);
        if ((threadIdx.x & 31) == 0) atomicAdd(&g_fg_s[b * 8 + n], v);
    }
}

// ---------------------------------------------------------------- Lovász scan
__global__ void __launch_bounds__(1024) k_scan() {
    int seg = blockIdx.x;
    int tid = threadIdx.x;
    int warp = tid >> 5, lane = tid & 31;
    __shared__ unsigned long long wsum[32];
    __shared__ float rs[32];

    double Pd = (double)g_acc[seg * 6 + 0];
    unsigned carry_p = 0, carry_n = 0;
    double lov = 0.0;
    const unsigned long long* hp = &g_hist[(size_t)seg * NBINS];

    for (int it = 0; it < NBINS / 1024; it++) {
        int bin = NBINS - 1 - (it * 1024 + tid);
        unsigned long long pair = hp[bin];
        unsigned nn = (unsigned)(pair & 0xffffffffu);
        unsigned np = (unsigned)(pair >> 32);
        unsigned long long inc = pair;
#pragma unroll
        for (int o = 1; o < 32; o <<= 1) {
            unsigned long long t = __shfl_up_sync(0xffffffffu, inc, o);
            if (lane >= o) inc += t;
        }
        if (lane == 31) wsum[warp] = inc;
        __syncthreads();
        if (warp == 0) {
            unsigned long long wv = wsum[lane];
#pragma unroll
            for (int o = 1; o < 32; o <<= 1) {
                unsigned long long t = __shfl_up_sync(0xffffffffu, wv, o);
                if (lane >= o) wv += t;
            }
            wsum[lane] = wv;
        }
        __syncthreads();
        unsigned long long incl = inc + (warp > 0 ? wsum[warp - 1] : 0ull);
        unsigned long long total = wsum[31];
        unsigned cp1 = carry_p + (unsigned)(incl >> 32);
        unsigned cn1 = carry_n + (unsigned)(incl & 0xffffffffu);
        unsigned cp0 = cp1 - np;
        unsigned cn0 = cn1 - nn;
        if (np | nn) {
            double j1 = 1.0 - (Pd - (double)cp1) / fmax(Pd + (double)cn1, 1.0);
            double j0 = 1.0 - (Pd - (double)cp0) / fmax(Pd + (double)cn0, 1.0);
            lov += ((double)bin + 0.5) * (1.0 / 16384.0) * (j1 - j0);
        }
        carry_p += (unsigned)(total >> 32);
        carry_n += (unsigned)(total & 0xffffffffu);
        __syncthreads();
    }
    float lf = wred((float)lov);
    if (lane == 0) rs[warp] = lf;
    __syncthreads();
    if (tid < 32) {
        float v = wred(rs[tid]);
        if (tid == 0) g_lov[seg] = v;
    }
}

// ---------------------------------------------------------------- final
__global__ void k_final(const int* __restrict__ cls_ids, float* __restrict__ out) {
    if (threadIdx.x == 0 && blockIdx.x == 0) {
        float total = 0.f;
        for (int b = 0; b < Bx; b++) {
            float obj = 0.f, inst = 0.f, var = 0.f, fg = 0.f;
            for (int n = 0; n < 8; n++) {
                int seg = b * 8 + n;
                float cnt = g_acc[seg * 6 + 0];
                float valid = (cnt >= MINPIX) ? 1.f : 0.f;
                float cs = fmaxf(cnt, 1.f);
                float S0 = g_acc[seg * 6 + 3];
                float S1 = g_acc[seg * 6 + 4];
                float Q  = g_acc[seg * 6 + 5];
                float vi = (Q - (S0 * S0 + S1 * S1) / cs) / (2.f * cs);
                obj += valid;
                inst += g_lov[seg] * valid;
                var += vi * valid;
                fg += FGW[cls_ids[seg]] * g_fg_s[seg] * valid;
            }
            float os = fmaxf(obj, 1.f);
            float seed_l = (g_seed_bg[b] + fg) * (1.0f / (float)HWx);
            total += inst / os + 10.f * (var / os) + seed_l;
        }
        out[0] = total * 0.5f;
    }
}

// ---------------------------------------------------------------- launch
// ncu profiles launch index 3 -> second k_sums4 this round.
extern "C" void kernel_launch(void* const* d_in, const int* in_sizes, int n_in,
                              void* d_out, int out_size) {
    const float* pred = (const float*)d_in[0];
    const int* bbox   = (const int*)d_in[1];
    const int* masks  = (const int*)d_in[2];
    const int* cls    = (const int*)d_in[3];
    (void)in_sizes; (void)n_in; (void)out_size;

    k_zero<<<512, 256>>>();                       // 0
    k_seed<<<Bx * BPB, 256>>>(pred, bbox);        // 1
    k_sums4<<<Bx * 512, 256>>>(pred, masks, 0);   // 2
    k_sums4<<<Bx * 512, 256>>>(pred, masks, 4);   // 3  <- profiled
    k_params<<<1, 32>>>();                        // 4
    k_pass3<<<Bx * BPB, 256>>>(pred, cls);        // 5
    k_scan<<<NSEG, 1024>>>();                     // 6
    k_final<<<1, 32>>>(cls, (float*)d_out);       // 7
}

// round 8
// speedup vs baseline: 1.7856x; 1.7856x over previous
#include <cuda_runtime.h>
#include <cuda_fp16.h>

#define Bx     2
#define Hx     512
#define Wx     1024
#define HWx    (Hx * Wx)          // 524288
#define NSEG   16
#define NBINS  32768
#define BIN_SCALE 16384.0f
#define MINPIX 128.0f
#define BPB    256                // blocks per batch for big passes

// ---- globals ----
__device__ __align__(16) unsigned long long g_hist[NSEG * NBINS]; // low=neg, high=pos
__device__ __align__(16) float g_acc[NSEG * 6];        // cnt, Se0, Se1, Ss0, Ss1, Q (by k_params)
__device__ __align__(16) float g_lov[NSEG];
__device__ __align__(16) float g_params[NSEG * 4];     // c0 c1 sx0 sx1
// per-block partials (no zero needed; fully overwritten each run)
__device__ __align__(16) float g_acc_part[96 * 256];   // [q][blk] q=(b*8+n)*6+j
__device__ __align__(16) float g_bg_part[2 * 256];     // [b][blk]
__device__ __align__(16) float g_fg_part[NSEG * 256];  // [seg][blk]
// scratch
__device__ __align__(16) __half g_seeds[Bx * 8 * HWx];       // [b][c][hw]
__device__ __align__(16) unsigned g_mbits[Bx * HWx / 4];     // byte j: bit n = mask n

__device__ const float FGW[8] = {10.0f, 10.0f, 10.0f, 40.0f, 80.0f, 100.0f, 60.0f, 20.0f};

__device__ __forceinline__ float wred(float v) {
    v += __shfl_down_sync(0xffffffffu, v, 16);
    v += __shfl_down_sync(0xffffffffu, v, 8);
    v += __shfl_down_sync(0xffffffffu, v, 4);
    v += __shfl_down_sync(0xffffffffu, v, 2);
    v += __shfl_down_sync(0xffffffffu, v, 1);
    return v;
}

__device__ __forceinline__ float tanh_approx(float x) {
    float r;
    asm("tanh.approx.f32 %0, %1;" : "=f"(r) : "f"(x));
    return r;
}
__device__ __forceinline__ __half2 sigmoid2_h(float a, float b) {
    __half2 x = __floats2half2_rn(0.5f * a, 0.5f * b);
    __half2 t;
    asm("tanh.approx.f16x2 %0, %1;" : "=r"(*(unsigned*)&t) : "r"(*(unsigned*)&x));
    const __half2 half2_half = __floats2half2_rn(0.5f, 0.5f);
    return __hfma2(t, half2_half, half2_half);
}

// ---------------------------------------------------------------- k_sums: masks + ch0-3 (launch 0)
__global__ void __launch_bounds__(256) k_sums(const float* __restrict__ pred,
                                              const int* __restrict__ masks) {
    int b = blockIdx.x / BPB;
    int blk = blockIdx.x % BPB;
    const float* pb = pred + (size_t)b * 12 * HWx;
    const int* mb  = masks + (size_t)b * 8 * HWx;
    unsigned* mbo = g_mbits + (size_t)b * HWx / 4;

    float acc[8][6];
#pragma unroll
    for (int n = 0; n < 8; n++)
#pragma unroll
        for (int j = 0; j < 6; j++) acc[n][j] = 0.f;

    for (int g = blk * 256 + threadIdx.x; g < HWx / 4; g += BPB * 256) {
        int hw = g * 4;
        int w = hw & (Wx - 1);
        int h = hw >> 10;
        float ybase = (float)h * (1.0f / 1023.0f);

        float4 p0 = *(const float4*)(pb + hw);
        float4 p1 = *(const float4*)(pb + HWx + hw);
        float4 s0v = *(const float4*)(pb + 2 * HWx + hw);
        float4 s1v = *(const float4*)(pb + 3 * HWx + hw);

        float e0[4], e1[4];
        e0[0] = tanh_approx(p0.x) + (float)(w + 0) * (2.0f / 2047.0f);
        e0[1] = tanh_approx(p0.y) + (float)(w + 1) * (2.0f / 2047.0f);
        e0[2] = tanh_approx(p0.z) + (float)(w + 2) * (2.0f / 2047.0f);
        e0[3] = tanh_approx(p0.w) + (float)(w + 3) * (2.0f / 2047.0f);
        e1[0] = tanh_approx(p1.x) + ybase;
        e1[1] = tanh_approx(p1.y) + ybase;
        e1[2] = tanh_approx(p1.z) + ybase;
        e1[3] = tanh_approx(p1.w) + ybase;
        float sg0[4] = {s0v.x, s0v.y, s0v.z, s0v.w};
        float sg1[4] = {s1v.x, s1v.y, s1v.z, s1v.w};
        float q4[4];
#pragma unroll
        for (int j = 0; j < 4; j++) q4[j] = fmaf(sg0[j], sg0[j], sg1[j] * sg1[j]);

        unsigned bits = 0;
#pragma unroll
        for (int n = 0; n < 8; n++) {
            int4 mv = *(const int4*)(mb + (size_t)n * HWx + hw);
            float mf[4];
            mf[0] = (mv.x > 0) ? 1.f : 0.f;
            mf[1] = (mv.y > 0) ? 1.f : 0.f;
            mf[2] = (mv.z > 0) ? 1.f : 0.f;
            mf[3] = (mv.w > 0) ? 1.f : 0.f;
#pragma unroll
            for (int j = 0; j < 4; j++) {
                acc[n][0] += mf[j];
                acc[n][1] = fmaf(mf[j], e0[j], acc[n][1]);
                acc[n][2] = fmaf(mf[j], e1[j], acc[n][2]);
                acc[n][3] = fmaf(mf[j], sg0[j], acc[n][3]);
                acc[n][4] = fmaf(mf[j], sg1[j], acc[n][4]);
                acc[n][5] = fmaf(mf[j], q4[j], acc[n][5]);
                if (mf[j] != 0.f) bits |= (1u << (n + j * 8));
            }
        }
        mbo[g] = bits;
    }

    // block-stage: warp reduce -> smem -> per-block partial STORE (no global atomics)
    __shared__ float s_red[48][8];
    int warp = threadIdx.x >> 5, lane = threadIdx.x & 31;
#pragma unroll
    for (int n = 0; n < 8; n++)
#pragma unroll
        for (int j = 0; j < 6; j++) {
            float v = wred(acc[n][j]);
            if (lane == 0) s_red[n * 6 + j][warp] = v;
        }
    __syncthreads();
    if (threadIdx.x < 48) {
        float s = 0.f;
#pragma unroll
        for (int wv = 0; wv < 8; wv++) s += s_red[threadIdx.x][wv];
        int q = (b * 8 + (threadIdx.x / 6)) * 6 + (threadIdx.x % 6);
        g_acc_part[q * 256 + blk] = s;
    }
}

// ---------------------------------------------------------------- k_params: reduce partials (launch 1)
__global__ void __launch_bounds__(256) k_params() {
    __shared__ float sq[96];
    int tid = threadIdx.x;
    int lane = tid & 31;
    if (tid < 96) sq[tid] = 0.f;
    __syncthreads();
    for (int q = 0; q < 96; q++) {
        float v = g_acc_part[q * 256 + tid];
        v = wred(v);
        if (lane == 0) atomicAdd(&sq[q], v);
    }
    __syncthreads();
    if (tid < NSEG) {
        float cnt = sq[tid * 6 + 0];
        float cs = fmaxf(cnt, 1.f);
        float inv = 1.f / cs;
#pragma unroll
        for (int j = 0; j < 6; j++) g_acc[tid * 6 + j] = sq[tid * 6 + j];
        g_params[tid * 4 + 0] = sq[tid * 6 + 1] * inv;
        g_params[tid * 4 + 1] = sq[tid * 6 + 2] * inv;
        g_params[tid * 4 + 2] = expf(sq[tid * 6 + 3] * inv * 10.f);
        g_params[tid * 4 + 3] = expf(sq[tid * 6 + 4] * inv * 10.f);
    }
}

// ---------------------------------------------------------------- k_seed: ch4-11 + bbox, also zeroes hist (launch 2)
__global__ void __launch_bounds__(256, 4) k_seed(const float* __restrict__ pred,
                                                 const int* __restrict__ bbox) {
    int b = blockIdx.x / BPB;
    int blk = blockIdx.x % BPB;
    const float* pb = pred + (size_t)b * 12 * HWx;
    const int* bbb = bbox + (size_t)b * 9 * HWx;
    __half* sdo = g_seeds + (size_t)b * 8 * HWx;

    // zero my slice of the histogram (4MB / 512 blocks = 8KB)
    {
        float4* hz = reinterpret_cast<float4*>(g_hist);
        int base = blockIdx.x * 512 + threadIdx.x;
        hz[base] = make_float4(0.f, 0.f, 0.f, 0.f);
        hz[base + 256] = make_float4(0.f, 0.f, 0.f, 0.f);
    }

    float bg = 0.f;
    for (int g = blk * 256 + threadIdx.x; g < HWx / 4; g += BPB * 256) {
        int hw = g * 4;
#pragma unroll
        for (int c = 0; c < 8; c++) {
            float4 sv = *(const float4*)(pb + (size_t)(4 + c) * HWx + hw);
            int4 bv = *(const int4*)(bbb + (size_t)(1 + c) * HWx + hw);
            __half2 s01 = sigmoid2_h(sv.x, sv.y);
            __half2 s23 = sigmoid2_h(sv.z, sv.w);
            float2 f01 = __half22float2(s01);
            float2 f23 = __half22float2(s23);
            if (bv.x == 0) bg = fmaf(f01.x, f01.x, bg);
            if (bv.y == 0) bg = fmaf(f01.y, f01.y, bg);
            if (bv.z == 0) bg = fmaf(f23.x, f23.x, bg);
            if (bv.w == 0) bg = fmaf(f23.y, f23.y, bg);
            uint2 pk;
            pk.x = *reinterpret_cast<unsigned*>(&s01);
            pk.y = *reinterpret_cast<unsigned*>(&s23);
            *(uint2*)(sdo + (size_t)c * HWx + hw) = pk;
        }
    }
    __shared__ float s_bg[8];
    int warp = threadIdx.x >> 5, lane = threadIdx.x & 31;
    bg = wred(bg);
    if (lane == 0) s_bg[warp] = bg;
    __syncthreads();
    if (threadIdx.x == 0) {
        float s = 0.f;
#pragma unroll
        for (int wv = 0; wv < 8; wv++) s += s_bg[wv];
        g_bg_part[b * 256 + blk] = s;
    }
}

// ---------------------------------------------------------------- pass3: dist, hist, seed_fg (launch 3 <- profiled)
__global__ void __launch_bounds__(256) k_pass3(const float* __restrict__ pred,
                                               const int* __restrict__ cls_ids) {
    int b = blockIdx.x / BPB;
    int blk = blockIdx.x % BPB;

    __shared__ float sp[8][4];
    __shared__ int sch[8];
    if (threadIdx.x < 32) {
        int n = threadIdx.x / 4, k = threadIdx.x % 4;
        sp[n][k] = g_params[(b * 8 + n) * 4 + k];
    }
    if (threadIdx.x < 8) sch[threadIdx.x] = cls_ids[b * 8 + threadIdx.x];
    __syncthreads();

    float c0[8], c1[8], sx0[8], sx1[8];
    const __half* sdp[8];
#pragma unroll
    for (int n = 0; n < 8; n++) {
        c0[n] = sp[n][0]; c1[n] = sp[n][1];
        sx0[n] = sp[n][2]; sx1[n] = sp[n][3];
        sdp[n] = g_seeds + ((size_t)b * 8 + sch[n]) * HWx;
    }
    float fa[8] = {0,0,0,0,0,0,0,0};

    const float* pb = pred + (size_t)b * 12 * HWx;
    const unsigned* mbi = g_mbits + (size_t)b * HWx / 4;
    unsigned long long* hb = &g_hist[(size_t)(b * 8) * NBINS];

    for (int g = blk * 256 + threadIdx.x; g < HWx / 4; g += BPB * 256) {
        int hw = g * 4;
        int w = hw & (Wx - 1);
        int h = hw >> 10;
        float ybase = (float)h * (1.0f / 1023.0f);
        float4 p0 = *(const float4*)(pb + hw);
        float4 p1 = *(const float4*)(pb + HWx + hw);
        float e0[4], e1[4];
        e0[0] = tanh_approx(p0.x) + (float)(w + 0) * (2.0f / 2047.0f);
        e0[1] = tanh_approx(p0.y) + (float)(w + 1) * (2.0f / 2047.0f);
        e0[2] = tanh_approx(p0.z) + (float)(w + 2) * (2.0f / 2047.0f);
        e0[3] = tanh_approx(p0.w) + (float)(w + 3) * (2.0f / 2047.0f);
        e1[0] = tanh_approx(p1.x) + ybase;
        e1[1] = tanh_approx(p1.y) + ybase;
        e1[2] = tanh_approx(p1.z) + ybase;
        e1[3] = tanh_approx(p1.w) + ybase;
        unsigned bits = mbi[g];

#pragma unroll
        for (int n = 0; n < 8; n++) {
            uint2 svp = *(const uint2*)(sdp[n] + hw);
            __half2 hA = *reinterpret_cast<__half2*>(&svp.x);
            __half2 hB = *reinterpret_cast<__half2*>(&svp.y);
            float2 fA = __half22float2(hA);
            float2 fB = __half22float2(hB);
            float sv[4] = {fA.x, fA.y, fB.x, fB.y};
#pragma unroll
            for (int j = 0; j < 4; j++) {
                int lab = (bits >> (n + j * 8)) & 1;
                float labf = (float)lab;
                float dx = e0[j] - c0[n];
                float dy = e1[j] - c1[n];
                float d2 = fmaf(dx * dx, sx0[n], dy * dy * sx1[n]);
                float dist = __expf(-d2);
                float eb = fabsf(dist - labf) * (2.0f * BIN_SCALE);
                int bin = min((int)eb, NBINS - 1);
                atomicAdd(&hb[(size_t)n * NBINS + bin],
                          lab ? (1ull << 32) : 1ull);
                float dd = sv[j] - dist;
                if (lab) fa[n] = fmaf(dd, dd, fa[n]);
            }
        }
    }

    // block-stage fg partials (no global atomics)
    __shared__ float s_fg[8][8];
    int warp = threadIdx.x >> 5, lane = threadIdx.x & 31;
#pragma unroll
    for (int n = 0; n < 8; n++) {
        float v = wred(fa[n]);
        if (lane == 0) s_fg[n][warp] = v;
    }
    __syncthreads();
    if (threadIdx.x < 8) {
        float s = 0.f;
#pragma unroll
        for (int wv = 0; wv < 8; wv++) s += s_fg[threadIdx.x][wv];
        g_fg_part[(b * 8 + threadIdx.x) * 256 + blk] = s;
    }
}

// ---------------------------------------------------------------- Lovász scan (launch 4)
__global__ void __launch_bounds__(1024) k_scan() {
    int seg = blockIdx.x;
    int tid = threadIdx.x;
    int warp = tid >> 5, lane = tid & 31;
    __shared__ unsigned long long wsum[32];
    __shared__ float rs[32];

    double Pd = (double)g_acc[seg * 6 + 0];
    unsigned carry_p = 0, carry_n = 0;
    double lov = 0.0;
    const unsigned long long* hp = &g_hist[(size_t)seg * NBINS];

    for (int it = 0; it < NBINS / 1024; it++) {
        int bin = NBINS - 1 - (it * 1024 + tid);
        unsigned long long pair = hp[bin];
        unsigned nn = (unsigned)(pair & 0xffffffffu);
        unsigned np = (unsigned)(pair >> 32);
        unsigned long long inc = pair;
#pragma unroll
        for (int o = 1; o < 32; o <<= 1) {
            unsigned long long t = __shfl_up_sync(0xffffffffu, inc, o);
            if (lane >= o) inc += t;
        }
        if (lane == 31) wsum[warp] = inc;
        __syncthreads();
        if (warp == 0) {
            unsigned long long wv = wsum[lane];
#pragma unroll
            for (int o = 1; o < 32; o <<= 1) {
                unsigned long long t = __shfl_up_sync(0xffffffffu, wv, o);
                if (lane >= o) wv += t;
            }
            wsum[lane] = wv;
        }
        __syncthreads();
        unsigned long long incl = inc + (warp > 0 ? wsum[warp - 1] : 0ull);
        unsigned long long total = wsum[31];
        unsigned cp1 = carry_p + (unsigned)(incl >> 32);
        unsigned cn1 = carry_n + (unsigned)(incl & 0xffffffffu);
        unsigned cp0 = cp1 - np;
        unsigned cn0 = cn1 - nn;
        if (np | nn) {
            double j1 = 1.0 - (Pd - (double)cp1) / fmax(Pd + (double)cn1, 1.0);
            double j0 = 1.0 - (Pd - (double)cp0) / fmax(Pd + (double)cn0, 1.0);
            lov += ((double)bin + 0.5) * (1.0 / 16384.0) * (j1 - j0);
        }
        carry_p += (unsigned)(total >> 32);
        carry_n += (unsigned)(total & 0xffffffffu);
        __syncthreads();
    }
    float lf = wred((float)lov);
    if (lane == 0) rs[warp] = lf;
    __syncthreads();
    if (tid < 32) {
        float v = wred(rs[tid]);
        if (tid == 0) g_lov[seg] = v;
    }
}

// ---------------------------------------------------------------- final (launch 5): reduce partials + combine
__global__ void __launch_bounds__(256) k_final(const int* __restrict__ cls_ids,
                                               float* __restrict__ out) {
    __shared__ float s_fg[NSEG];
    __shared__ float s_bg[Bx];
    int tid = threadIdx.x, lane = tid & 31;
    if (tid < NSEG) s_fg[tid] = 0.f;
    if (tid < Bx) s_bg[tid] = 0.f;
    __syncthreads();
    for (int seg = 0; seg < NSEG; seg++) {
        float v = g_fg_part[seg * 256 + tid];
        v = wred(v);
        if (lane == 0) atomicAdd(&s_fg[seg], v);
    }
    for (int b = 0; b < Bx; b++) {
        float v = g_bg_part[b * 256 + tid];
        v = wred(v);
        if (lane == 0) atomicAdd(&s_bg[b], v);
    }
    __syncthreads();
    if (tid == 0) {
        float total = 0.f;
        for (int b = 0; b < Bx; b++) {
            float obj = 0.f, inst = 0.f, var = 0.f, fg = 0.f;
            for (int n = 0; n < 8; n++) {
                int seg = b * 8 + n;
                float cnt = g_acc[seg * 6 + 0];
                float valid = (cnt >= MINPIX) ? 1.f : 0.f;
                float cs = fmaxf(cnt, 1.f);
                float S0 = g_acc[seg * 6 + 3];
                float S1 = g_acc[seg * 6 + 4];
                float Q  = g_acc[seg * 6 + 5];
                float vi = (Q - (S0 * S0 + S1 * S1) / cs) / (2.f * cs);
                obj += valid;
                inst += g_lov[seg] * valid;
                var += vi * valid;
                fg += FGW[cls_ids[seg]] * s_fg[seg] * valid;
            }
            float os = fmaxf(obj, 1.f);
            float seed_l = (s_bg[b] + fg) * (1.0f / (float)HWx);
            total += inst / os + 10.f * (var / os) + seed_l;
        }
        out[0] = total * 0.5f;
    }
}

// ---------------------------------------------------------------- launch
// ncu profiles launch index 3 -> k_pass3 this round (the suspected hog).
extern "C" void kernel_launch(void* const* d_in, const int* in_sizes, int n_in,
                              void* d_out, int out_size) {
    const float* pred = (const float*)d_in[0];
    const int* bbox   = (const int*)d_in[1];
    const int* masks  = (const int*)d_in[2];
    const int* cls    = (const int*)d_in[3];
    (void)in_sizes; (void)n_in; (void)out_size;

    k_sums<<<Bx * BPB, 256>>>(pred, masks);       // 0
    k_params<<<1, 256>>>();                       // 1
    k_seed<<<Bx * BPB, 256>>>(pred, bbox);        // 2  (also zeroes hist)
    k_pass3<<<Bx * BPB, 256>>>(pred, cls);        // 3  <- profiled
    k_scan<<<NSEG, 1024>>>();                     // 4
    k_final<<<1, 256>>>(cls, (float*)d_out);      // 5
}

// round 9
// speedup vs baseline: 1.8350x; 1.0277x over previous
#include <cuda_runtime.h>
#include <cuda_fp16.h>

#define Bx     2
#define Hx     512
#define Wx     1024
#define HWx    (Hx * Wx)          // 524288
#define NSEG   16
#define NBINS  32768
#define BIN_SCALE 16384.0f
#define MINPIX 128.0f
#define BPB    256                // blocks per batch for big passes

// ---- globals ----
__device__ __align__(16) unsigned long long g_hist[NSEG * NBINS]; // low=neg, high=pos
__device__ __align__(16) float g_acc[NSEG * 6];        // cnt, Se0, Se1, Ss0, Ss1, Q
__device__ __align__(16) float g_lov[NSEG];
__device__ __align__(16) float g_params[NSEG * 4];     // c0 c1 sx0 sx1
// per-block partials (fully overwritten each run; no zeroing needed)
__device__ __align__(16) float g_acc_part[96 * 256];   // [q][blk] q=(b*8+n)*6+j
__device__ __align__(16) float g_bg_part[2 * 256];     // [b][blk]
__device__ __align__(16) float g_fg_part[NSEG * 256];  // [seg][blk]
// scratch
__device__ __align__(16) __half g_seeds[Bx * 8 * HWx];       // [b][c][hw]
__device__ __align__(16) unsigned g_mbits[Bx * HWx / 4];     // byte j: bit n = mask n

__device__ const float FGW[8] = {10.0f, 10.0f, 10.0f, 40.0f, 80.0f, 100.0f, 60.0f, 20.0f};

__device__ __forceinline__ float wred(float v) {
    v += __shfl_down_sync(0xffffffffu, v, 16);
    v += __shfl_down_sync(0xffffffffu, v, 8);
    v += __shfl_down_sync(0xffffffffu, v, 4);
    v += __shfl_down_sync(0xffffffffu, v, 2);
    v += __shfl_down_sync(0xffffffffu, v, 1);
    return v;
}

__device__ __forceinline__ float tanh_approx(float x) {
    float r;
    asm("tanh.approx.f32 %0, %1;" : "=f"(r) : "f"(x));
    return r;
}
__device__ __forceinline__ __half2 sigmoid2_h(float a, float b) {
    __half2 x = __floats2half2_rn(0.5f * a, 0.5f * b);
    __half2 t;
    asm("tanh.approx.f16x2 %0, %1;" : "=r"(*(unsigned*)&t) : "r"(*(unsigned*)&x));
    const __half2 half2_half = __floats2half2_rn(0.5f, 0.5f);
    return __hfma2(t, half2_half, half2_half);
}

// ---------------------------------------------------------------- k_seed: ch4-11 + bbox (launch 0)
__global__ void __launch_bounds__(256, 4) k_seed(const float* __restrict__ pred,
                                                 const int* __restrict__ bbox) {
    int b = blockIdx.x / BPB;
    int blk = blockIdx.x % BPB;
    const float* pb = pred + (size_t)b * 12 * HWx;
    const int* bbb = bbox + (size_t)b * 9 * HWx;
    __half* sdo = g_seeds + (size_t)b * 8 * HWx;

    float bg = 0.f;
    for (int g = blk * 256 + threadIdx.x; g < HWx / 4; g += BPB * 256) {
        int hw = g * 4;
#pragma unroll
        for (int c = 0; c < 8; c++) {
            float4 sv = *(const float4*)(pb + (size_t)(4 + c) * HWx + hw);
            int4 bv = *(const int4*)(bbb + (size_t)(1 + c) * HWx + hw);
            __half2 s01 = sigmoid2_h(sv.x, sv.y);
            __half2 s23 = sigmoid2_h(sv.z, sv.w);
            float2 f01 = __half22float2(s01);
            float2 f23 = __half22float2(s23);
            if (bv.x == 0) bg = fmaf(f01.x, f01.x, bg);
            if (bv.y == 0) bg = fmaf(f01.y, f01.y, bg);
            if (bv.z == 0) bg = fmaf(f23.x, f23.x, bg);
            if (bv.w == 0) bg = fmaf(f23.y, f23.y, bg);
            uint2 pk;
            pk.x = *reinterpret_cast<unsigned*>(&s01);
            pk.y = *reinterpret_cast<unsigned*>(&s23);
            *(uint2*)(sdo + (size_t)c * HWx + hw) = pk;
        }
    }
    __shared__ float s_bg[8];
    int warp = threadIdx.x >> 5, lane = threadIdx.x & 31;
    bg = wred(bg);
    if (lane == 0) s_bg[warp] = bg;
    __syncthreads();
    if (threadIdx.x == 0) {
        float s = 0.f;
#pragma unroll
        for (int wv = 0; wv < 8; wv++) s += s_bg[wv];
        g_bg_part[b * 256 + blk] = s;
    }
}

// ---------------------------------------------------------------- k_bits: masks -> mbits (launch 1)
__global__ void __launch_bounds__(256, 4) k_bits(const int* __restrict__ masks) {
    int b = blockIdx.x / BPB;
    int blk = blockIdx.x % BPB;
    const int* mb = masks + (size_t)b * 8 * HWx;
    unsigned* mbo = g_mbits + (size_t)b * HWx / 4;

    for (int g = blk * 256 + threadIdx.x; g < HWx / 4; g += BPB * 256) {
        int hw = g * 4;
        unsigned bits = 0;
#pragma unroll
        for (int n = 0; n < 8; n++) {
            int4 mv = *(const int4*)(mb + (size_t)n * HWx + hw);
            if (mv.x > 0) bits |= (1u << (n + 0));
            if (mv.y > 0) bits |= (1u << (n + 8));
            if (mv.z > 0) bits |= (1u << (n + 16));
            if (mv.w > 0) bits |= (1u << (n + 24));
        }
        mbo[g] = bits;
    }
}

// ---------------------------------------------------------------- k_zero_hist (launch 2)
__global__ void __launch_bounds__(256) k_zero_hist() {
    float4* hz = reinterpret_cast<float4*>(g_hist);
    hz[blockIdx.x * 256 + threadIdx.x] = make_float4(0.f, 0.f, 0.f, 0.f);
}

// ---------------------------------------------------------------- k_accum: ch0-3 + mbits -> sums (launch 3, profiled)
__global__ void __launch_bounds__(256) k_accum(const float* __restrict__ pred) {
    int b = blockIdx.x / BPB;
    int blk = blockIdx.x % BPB;
    const float* pb = pred + (size_t)b * 12 * HWx;
    const unsigned* mbi = g_mbits + (size_t)b * HWx / 4;

    float acc[8][5];   // Se0, Se1, Ss0, Ss1, Q
    int cnt[8];
#pragma unroll
    for (int n = 0; n < 8; n++) {
        cnt[n] = 0;
#pragma unroll
        for (int j = 0; j < 5; j++) acc[n][j] = 0.f;
    }

    for (int g = blk * 256 + threadIdx.x; g < HWx / 4; g += BPB * 256) {
        int hw = g * 4;
        int w = hw & (Wx - 1);
        int h = hw >> 10;
        float ybase = (float)h * (1.0f / 1023.0f);

        unsigned bits = mbi[g];
        float4 p0 = *(const float4*)(pb + hw);
        float4 p1 = *(const float4*)(pb + HWx + hw);
        float4 s0v = *(const float4*)(pb + 2 * HWx + hw);
        float4 s1v = *(const float4*)(pb + 3 * HWx + hw);

        float e0[4], e1[4];
        e0[0] = tanh_approx(p0.x) + (float)(w + 0) * (2.0f / 2047.0f);
        e0[1] = tanh_approx(p0.y) + (float)(w + 1) * (2.0f / 2047.0f);
        e0[2] = tanh_approx(p0.z) + (float)(w + 2) * (2.0f / 2047.0f);
        e0[3] = tanh_approx(p0.w) + (float)(w + 3) * (2.0f / 2047.0f);
        e1[0] = tanh_approx(p1.x) + ybase;
        e1[1] = tanh_approx(p1.y) + ybase;
        e1[2] = tanh_approx(p1.z) + ybase;
        e1[3] = tanh_approx(p1.w) + ybase;
        float sg0[4] = {s0v.x, s0v.y, s0v.z, s0v.w};
        float sg1[4] = {s1v.x, s1v.y, s1v.z, s1v.w};
        float q4[4];
#pragma unroll
        for (int j = 0; j < 4; j++) q4[j] = fmaf(sg0[j], sg0[j], sg1[j] * sg1[j]);

#pragma unroll
        for (int n = 0; n < 8; n++) {
            cnt[n] += __popc(bits & (0x01010101u << n));
#pragma unroll
            for (int j = 0; j < 4; j++) {
                if ((bits >> (n + j * 8)) & 1u) {
                    acc[n][0] += e0[j];
                    acc[n][1] += e1[j];
                    acc[n][2] += sg0[j];
                    acc[n][3] += sg1[j];
                    acc[n][4] += q4[j];
                }
            }
        }
    }

    __shared__ float s_red[48][8];
    int warp = threadIdx.x >> 5, lane = threadIdx.x & 31;
#pragma unroll
    for (int n = 0; n < 8; n++) {
        float v;
        v = wred((float)cnt[n]); if (lane == 0) s_red[n * 6 + 0][warp] = v;
#pragma unroll
        for (int j = 0; j < 5; j++) {
            v = wred(acc[n][j]);
            if (lane == 0) s_red[n * 6 + 1 + j][warp] = v;
        }
    }
    __syncthreads();
    if (threadIdx.x < 48) {
        float s = 0.f;
#pragma unroll
        for (int wv = 0; wv < 8; wv++) s += s_red[threadIdx.x][wv];
        int q = (b * 8 + (threadIdx.x / 6)) * 6 + (threadIdx.x % 6);
        g_acc_part[q * 256 + blk] = s;
    }
}

// ---------------------------------------------------------------- k_params: reduce partials (launch 4)
__global__ void __launch_bounds__(1024) k_params() {
    __shared__ float sq[96];
    int warp = threadIdx.x >> 5, lane = threadIdx.x & 31;
    for (int q = warp; q < 96; q += 32) {
        float v = 0.f;
#pragma unroll
        for (int i = 0; i < 8; i++) v += g_acc_part[q * 256 + lane + i * 32];
        v = wred(v);
        if (lane == 0) sq[q] = v;
    }
    __syncthreads();
    int tid = threadIdx.x;
    if (tid < NSEG) {
        float cnt = sq[tid * 6 + 0];
        float cs = fmaxf(cnt, 1.f);
        float inv = 1.f / cs;
#pragma unroll
        for (int j = 0; j < 6; j++) g_acc[tid * 6 + j] = sq[tid * 6 + j];
        g_params[tid * 4 + 0] = sq[tid * 6 + 1] * inv;
        g_params[tid * 4 + 1] = sq[tid * 6 + 2] * inv;
        g_params[tid * 4 + 2] = expf(sq[tid * 6 + 3] * inv * 10.f);
        g_params[tid * 4 + 3] = expf(sq[tid * 6 + 4] * inv * 10.f);
    }
}

// ---------------------------------------------------------------- pass3: dist, hist, seed_fg (launch 5)
__global__ void __launch_bounds__(256) k_pass3(const float* __restrict__ pred,
                                               const int* __restrict__ cls_ids) {
    int b = blockIdx.x / BPB;
    int blk = blockIdx.x % BPB;

    __shared__ float sp[8][4];
    __shared__ int sch[8];
    if (threadIdx.x < 32) {
        int n = threadIdx.x / 4, k = threadIdx.x % 4;
        sp[n][k] = g_params[(b * 8 + n) * 4 + k];
    }
    if (threadIdx.x < 8) sch[threadIdx.x] = cls_ids[b * 8 + threadIdx.x];
    __syncthreads();

    float c0[8], c1[8], sx0[8], sx1[8];
    const __half* sdp[8];
#pragma unroll
    for (int n = 0; n < 8; n++) {
        c0[n] = sp[n][0]; c1[n] = sp[n][1];
        sx0[n] = sp[n][2]; sx1[n] = sp[n][3];
        sdp[n] = g_seeds + ((size_t)b * 8 + sch[n]) * HWx;
    }
    float fa[8] = {0,0,0,0,0,0,0,0};

    const float* pb = pred + (size_t)b * 12 * HWx;
    const unsigned* mbi = g_mbits + (size_t)b * HWx / 4;
    unsigned long long* hb = &g_hist[(size_t)(b * 8) * NBINS];

    for (int g = blk * 256 + threadIdx.x; g < HWx / 4; g += BPB * 256) {
        int hw = g * 4;
        int w = hw & (Wx - 1);
        int h = hw >> 10;
        float ybase = (float)h * (1.0f / 1023.0f);
        float4 p0 = *(const float4*)(pb + hw);
        float4 p1 = *(const float4*)(pb + HWx + hw);
        float e0[4], e1[4];
        e0[0] = tanh_approx(p0.x) + (float)(w + 0) * (2.0f / 2047.0f);
        e0[1] = tanh_approx(p0.y) + (float)(w + 1) * (2.0f / 2047.0f);
        e0[2] = tanh_approx(p0.z) + (float)(w + 2) * (2.0f / 2047.0f);
        e0[3] = tanh_approx(p0.w) + (float)(w + 3) * (2.0f / 2047.0f);
        e1[0] = tanh_approx(p1.x) + ybase;
        e1[1] = tanh_approx(p1.y) + ybase;
        e1[2] = tanh_approx(p1.z) + ybase;
        e1[3] = tanh_approx(p1.w) + ybase;
        unsigned bits = mbi[g];

#pragma unroll
        for (int n = 0; n < 8; n++) {
            uint2 svp = *(const uint2*)(sdp[n] + hw);
            __half2 hA = *reinterpret_cast<__half2*>(&svp.x);
            __half2 hB = *reinterpret_cast<__half2*>(&svp.y);
            float2 fA = __half22float2(hA);
            float2 fB = __half22float2(hB);
            float sv[4] = {fA.x, fA.y, fB.x, fB.y};
#pragma unroll
            for (int j = 0; j < 4; j++) {
                int lab = (bits >> (n + j * 8)) & 1;
                float labf = (float)lab;
                float dx = e0[j] - c0[n];
                float dy = e1[j] - c1[n];
                float d2 = fmaf(dx * dx, sx0[n], dy * dy * sx1[n]);
                float dist = __expf(-d2);
                float eb = fabsf(dist - labf) * (2.0f * BIN_SCALE);
                int bin = min((int)eb, NBINS - 1);
                atomicAdd(&hb[(size_t)n * NBINS + bin],
                          lab ? (1ull << 32) : 1ull);
                float dd = sv[j] - dist;
                if (lab) fa[n] = fmaf(dd, dd, fa[n]);
            }
        }
    }

    __shared__ float s_fg[8][8];
    int warp = threadIdx.x >> 5, lane = threadIdx.x & 31;
#pragma unroll
    for (int n = 0; n < 8; n++) {
        float v = wred(fa[n]);
        if (lane == 0) s_fg[n][warp] = v;
    }
    __syncthreads();
    if (threadIdx.x < 8) {
        float s = 0.f;
#pragma unroll
        for (int wv = 0; wv < 8; wv++) s += s_fg[threadIdx.x][wv];
        g_fg_part[(b * 8 + threadIdx.x) * 256 + blk] = s;
    }
}

// ---------------------------------------------------------------- Lovász scan (launch 6)
__global__ void __launch_bounds__(1024) k_scan() {
    int seg = blockIdx.x;
    int tid = threadIdx.x;
    int warp = tid >> 5, lane = tid & 31;
    __shared__ unsigned long long wsum[32];
    __shared__ float rs[32];

    double Pd = (double)g_acc[seg * 6 + 0];
    unsigned carry_p = 0, carry_n = 0;
    double lov = 0.0;
    const unsigned long long* hp = &g_hist[(size_t)seg * NBINS];

    for (int it = 0; it < NBINS / 1024; it++) {
        int bin = NBINS - 1 - (it * 1024 + tid);
        unsigned long long pair = hp[bin];
        unsigned nn = (unsigned)(pair & 0xffffffffu);
        unsigned np = (unsigned)(pair >> 32);
        unsigned long long inc = pair;
#pragma unroll
        for (int o = 1; o < 32; o <<= 1) {
            unsigned long long t = __shfl_up_sync(0xffffffffu, inc, o);
            if (lane >= o) inc += t;
        }
        if (lane == 31) wsum[warp] = inc;
        __syncthreads();
        if (warp == 0) {
            unsigned long long wv = wsum[lane];
#pragma unroll
            for (int o = 1; o < 32; o <<= 1) {
                unsigned long long t = __shfl_up_sync(0xffffffffu, wv, o);
                if (lane >= o) wv += t;
            }
            wsum[lane] = wv;
        }
        __syncthreads();
        unsigned long long incl = inc + (warp > 0 ? wsum[warp - 1] : 0ull);
        unsigned long long total = wsum[31];
        unsigned cp1 = carry_p + (unsigned)(incl >> 32);
        unsigned cn1 = carry_n + (unsigned)(incl & 0xffffffffu);
        unsigned cp0 = cp1 - np;
        unsigned cn0 = cn1 - nn;
        if (np | nn) {
            double j1 = 1.0 - (Pd - (double)cp1) / fmax(Pd + (double)cn1, 1.0);
            double j0 = 1.0 - (Pd - (double)cp0) / fmax(Pd + (double)cn0, 1.0);
            lov += ((double)bin + 0.5) * (1.0 / 16384.0) * (j1 - j0);
        }
        carry_p += (unsigned)(total >> 32);
        carry_n += (unsigned)(total & 0xffffffffu);
        __syncthreads();
    }
    float lf = wred((float)lov);
    if (lane == 0) rs[warp] = lf;
    __syncthreads();
    if (tid < 32) {
        float v = wred(rs[tid]);
        if (tid == 0) g_lov[seg] = v;
    }
}

// ---------------------------------------------------------------- final (launch 7)
__global__ void __launch_bounds__(1024) k_final(const int* __restrict__ cls_ids,
                                                float* __restrict__ out) {
    __shared__ float s_fg[NSEG];
    __shared__ float s_bg[Bx];
    int warp = threadIdx.x >> 5, lane = threadIdx.x & 31;
    if (warp < NSEG) {
        float v = 0.f;
#pragma unroll
        for (int i = 0; i < 8; i++) v += g_fg_part[warp * 256 + lane + i * 32];
        v = wred(v);
        if (lane == 0) s_fg[warp] = v;
    } else if (warp < NSEG + Bx) {
        int b = warp - NSEG;
        float v = 0.f;
#pragma unroll
        for (int i = 0; i < 8; i++) v += g_bg_part[b * 256 + lane + i * 32];
        v = wred(v);
        if (lane == 0) s_bg[b] = v;
    }
    __syncthreads();
    if (threadIdx.x == 0) {
        float total = 0.f;
        for (int b = 0; b < Bx; b++) {
            float obj = 0.f, inst = 0.f, var = 0.f, fg = 0.f;
            for (int n = 0; n < 8; n++) {
                int seg = b * 8 + n;
                float cnt = g_acc[seg * 6 + 0];
                float valid = (cnt >= MINPIX) ? 1.f : 0.f;
                float cs = fmaxf(cnt, 1.f);
                float S0 = g_acc[seg * 6 + 3];
                float S1 = g_acc[seg * 6 + 4];
                float Q  = g_acc[seg * 6 + 5];
                float vi = (Q - (S0 * S0 + S1 * S1) / cs) / (2.f * cs);
                obj += valid;
                inst += g_lov[seg] * valid;
                var += vi * valid;
                fg += FGW[cls_ids[seg]] * s_fg[seg] * valid;
            }
            float os = fmaxf(obj, 1.f);
            float seed_l = (s_bg[b] + fg) * (1.0f / (float)HWx);
            total += inst / os + 10.f * (var / os) + seed_l;
        }
        out[0] = total * 0.5f;
    }
}

// ---------------------------------------------------------------- launch
// ncu profiles launch index 3 -> k_accum (the isolated accumulation kernel).
extern "C" void kernel_launch(void* const* d_in, const int* in_sizes, int n_in,
                              void* d_out, int out_size) {
    const float* pred = (const float*)d_in[0];
    const int* bbox   = (const int*)d_in[1];
    const int* masks  = (const int*)d_in[2];
    const int* cls    = (const int*)d_in[3];
    (void)in_sizes; (void)n_in; (void)out_size;

    k_seed<<<Bx * BPB, 256>>>(pred, bbox);        // 0
    k_bits<<<Bx * BPB, 256>>>(masks);             // 1
    k_zero_hist<<<1024, 256>>>();                 // 2
    k_accum<<<Bx * BPB, 256>>>(pred);             // 3  <- profiled
    k_params<<<1, 1024>>>();                      // 4
    k_pass3<<<Bx * BPB, 256>>>(pred, cls);        // 5
    k_scan<<<NSEG, 1024>>>();                     // 6
    k_final<<<1, 1024>>>(cls, (float*)d_out);     // 7
}

// round 10
// speedup vs baseline: 6.3976x; 3.4864x over previous
#include <cuda_runtime.h>
#include <cuda_fp16.h>

#define Bx     2
#define Hx     512
#define Wx     1024
#define HWx    (Hx * Wx)          // 524288
#define NSEG   16
#define NBINS  32768
#define BIN_SCALE 16384.0f
#define MINPIX 128.0f
#define BPB    256                // blocks per batch for big passes

// ---- globals ----
__device__ __align__(16) unsigned long long g_hist[NSEG * NBINS]; // low=neg, high=pos
__device__ __align__(16) float g_acc[NSEG * 6];        // cnt, Se0, Se1, Ss0, Ss1, Q
__device__ __align__(16) float g_lov[NSEG];
__device__ __align__(16) float g_params[NSEG * 4];     // c0 c1 sx0 sx1
// per-block partials (fully overwritten each run; no zeroing needed)
__device__ __align__(16) float g_acc_part[96 * 256];   // [q][blk] q=(b*8+n)*6+j
__device__ __align__(16) float g_bg_part[2 * 256];     // [b][blk]
__device__ __align__(16) float g_fg_part[NSEG * 256];  // [seg][blk]
// scratch
__device__ __align__(16) __half g_seeds[Bx * 8 * HWx];       // [b][c][hw]
__device__ __align__(16) unsigned g_mbits[Bx * HWx / 4];     // byte j: bit n = mask n

__device__ const float FGW[8] = {10.0f, 10.0f, 10.0f, 40.0f, 80.0f, 100.0f, 60.0f, 20.0f};

__device__ __forceinline__ float wred(float v) {
    v += __shfl_down_sync(0xffffffffu, v, 16);
    v += __shfl_down_sync(0xffffffffu, v, 8);
    v += __shfl_down_sync(0xffffffffu, v, 4);
    v += __shfl_down_sync(0xffffffffu, v, 2);
    v += __shfl_down_sync(0xffffffffu, v, 1);
    return v;
}

__device__ __forceinline__ float tanh_approx(float x) {
    float r;
    asm("tanh.approx.f32 %0, %1;" : "=f"(r) : "f"(x));
    return r;
}
__device__ __forceinline__ __half2 sigmoid2_h(float a, float b) {
    __half2 x = __floats2half2_rn(0.5f * a, 0.5f * b);
    __half2 t;
    asm("tanh.approx.f16x2 %0, %1;" : "=r"(*(unsigned*)&t) : "r"(*(unsigned*)&x));
    const __half2 half2_half = __floats2half2_rn(0.5f, 0.5f);
    return __hfma2(t, half2_half, half2_half);
}

// ---------------------------------------------------------------- k_seed: ch4-11 + bbox, zeroes hist (launch 0)
__global__ void __launch_bounds__(256, 4) k_seed(const float* __restrict__ pred,
                                                 const int* __restrict__ bbox) {
    int b = blockIdx.x / BPB;
    int blk = blockIdx.x % BPB;
    const float* pb = pred + (size_t)b * 12 * HWx;
    const int* bbb = bbox + (size_t)b * 9 * HWx;
    __half* sdo = g_seeds + (size_t)b * 8 * HWx;

    // zero my slice of the histogram (4MB over 512 blocks = 8KB each)
    {
        float4* hz = reinterpret_cast<float4*>(g_hist);
        int base = blockIdx.x * 512 + threadIdx.x;
        hz[base] = make_float4(0.f, 0.f, 0.f, 0.f);
        hz[base + 256] = make_float4(0.f, 0.f, 0.f, 0.f);
    }

    float bg = 0.f;
    for (int g = blk * 256 + threadIdx.x; g < HWx / 4; g += BPB * 256) {
        int hw = g * 4;
#pragma unroll
        for (int c = 0; c < 8; c++) {
            float4 sv = *(const float4*)(pb + (size_t)(4 + c) * HWx + hw);
            int4 bv = *(const int4*)(bbb + (size_t)(1 + c) * HWx + hw);
            __half2 s01 = sigmoid2_h(sv.x, sv.y);
            __half2 s23 = sigmoid2_h(sv.z, sv.w);
            float2 f01 = __half22float2(s01);
            float2 f23 = __half22float2(s23);
            if (bv.x == 0) bg = fmaf(f01.x, f01.x, bg);
            if (bv.y == 0) bg = fmaf(f01.y, f01.y, bg);
            if (bv.z == 0) bg = fmaf(f23.x, f23.x, bg);
            if (bv.w == 0) bg = fmaf(f23.y, f23.y, bg);
            uint2 pk;
            pk.x = *reinterpret_cast<unsigned*>(&s01);
            pk.y = *reinterpret_cast<unsigned*>(&s23);
            *(uint2*)(sdo + (size_t)c * HWx + hw) = pk;
        }
    }
    __shared__ float s_bg[8];
    int warp = threadIdx.x >> 5, lane = threadIdx.x & 31;
    bg = wred(bg);
    if (lane == 0) s_bg[warp] = bg;
    __syncthreads();
    if (threadIdx.x == 0) {
        float s = 0.f;
#pragma unroll
        for (int wv = 0; wv < 8; wv++) s += s_bg[wv];
        g_bg_part[b * 256 + blk] = s;
    }
}

// ---------------------------------------------------------------- k_bits: masks -> mbits (launch 1)
__global__ void __launch_bounds__(256, 4) k_bits(const int* __restrict__ masks) {
    int b = blockIdx.x / BPB;
    int blk = blockIdx.x % BPB;
    const int* mb = masks + (size_t)b * 8 * HWx;
    unsigned* mbo = g_mbits + (size_t)b * HWx / 4;

    for (int g = blk * 256 + threadIdx.x; g < HWx / 4; g += BPB * 256) {
        int hw = g * 4;
        unsigned bits = 0;
#pragma unroll
        for (int n = 0; n < 8; n++) {
            int4 mv = *(const int4*)(mb + (size_t)n * HWx + hw);
            if (mv.x > 0) bits |= (1u << (n + 0));
            if (mv.y > 0) bits |= (1u << (n + 8));
            if (mv.z > 0) bits |= (1u << (n + 16));
            if (mv.w > 0) bits |= (1u << (n + 24));
        }
        mbo[g] = bits;
    }
}

// ---------------------------------------------------------------- k_accum: ch0-3 + mbits -> sums (launch 2)
__global__ void __launch_bounds__(256) k_accum(const float* __restrict__ pred) {
    int b = blockIdx.x / BPB;
    int blk = blockIdx.x % BPB;
    const float* pb = pred + (size_t)b * 12 * HWx;
    const unsigned* mbi = g_mbits + (size_t)b * HWx / 4;

    float acc[8][5];   // Se0, Se1, Ss0, Ss1, Q
    int cnt[8];
#pragma unroll
    for (int n = 0; n < 8; n++) {
        cnt[n] = 0;
#pragma unroll
        for (int j = 0; j < 5; j++) acc[n][j] = 0.f;
    }

    for (int g = blk * 256 + threadIdx.x; g < HWx / 4; g += BPB * 256) {
        int hw = g * 4;
        int w = hw & (Wx - 1);
        int h = hw >> 10;
        float ybase = (float)h * (1.0f / 1023.0f);

        unsigned bits = mbi[g];
        float4 p0 = *(const float4*)(pb + hw);
        float4 p1 = *(const float4*)(pb + HWx + hw);
        float4 s0v = *(const float4*)(pb + 2 * HWx + hw);
        float4 s1v = *(const float4*)(pb + 3 * HWx + hw);

        float e0[4], e1[4];
        e0[0] = tanh_approx(p0.x) + (float)(w + 0) * (2.0f / 2047.0f);
        e0[1] = tanh_approx(p0.y) + (float)(w + 1) * (2.0f / 2047.0f);
        e0[2] = tanh_approx(p0.z) + (float)(w + 2) * (2.0f / 2047.0f);
        e0[3] = tanh_approx(p0.w) + (float)(w + 3) * (2.0f / 2047.0f);
        e1[0] = tanh_approx(p1.x) + ybase;
        e1[1] = tanh_approx(p1.y) + ybase;
        e1[2] = tanh_approx(p1.z) + ybase;
        e1[3] = tanh_approx(p1.w) + ybase;
        float sg0[4] = {s0v.x, s0v.y, s0v.z, s0v.w};
        float sg1[4] = {s1v.x, s1v.y, s1v.z, s1v.w};
        float q4[4];
#pragma unroll
        for (int j = 0; j < 4; j++) q4[j] = fmaf(sg0[j], sg0[j], sg1[j] * sg1[j]);

#pragma unroll
        for (int n = 0; n < 8; n++) {
            cnt[n] += __popc(bits & (0x01010101u << n));
#pragma unroll
            for (int j = 0; j < 4; j++) {
                if ((bits >> (n + j * 8)) & 1u) {
                    acc[n][0] += e0[j];
                    acc[n][1] += e1[j];
                    acc[n][2] += sg0[j];
                    acc[n][3] += sg1[j];
                    acc[n][4] += q4[j];
                }
            }
        }
    }

    __shared__ float s_red[48][8];
    int warp = threadIdx.x >> 5, lane = threadIdx.x & 31;
#pragma unroll
    for (int n = 0; n < 8; n++) {
        float v;
        v = wred((float)cnt[n]); if (lane == 0) s_red[n * 6 + 0][warp] = v;
#pragma unroll
        for (int j = 0; j < 5; j++) {
            v = wred(acc[n][j]);
            if (lane == 0) s_red[n * 6 + 1 + j][warp] = v;
        }
    }
    __syncthreads();
    if (threadIdx.x < 48) {
        float s = 0.f;
#pragma unroll
        for (int wv = 0; wv < 8; wv++) s += s_red[threadIdx.x][wv];
        int q = (b * 8 + (threadIdx.x / 6)) * 6 + (threadIdx.x % 6);
        g_acc_part[q * 256 + blk] = s;
    }
}

// ---------------------------------------------------------------- k_params: reduce partials (launch 3)
__global__ void __launch_bounds__(1024) k_params() {
    __shared__ float sq[96];
    int warp = threadIdx.x >> 5, lane = threadIdx.x & 31;
    for (int q = warp; q < 96; q += 32) {
        float v = 0.f;
#pragma unroll
        for (int i = 0; i < 8; i++) v += g_acc_part[q * 256 + lane + i * 32];
        v = wred(v);
        if (lane == 0) sq[q] = v;
    }
    __syncthreads();
    int tid = threadIdx.x;
    if (tid < NSEG) {
        float cnt = sq[tid * 6 + 0];
        float cs = fmaxf(cnt, 1.f);
        float inv = 1.f / cs;
#pragma unroll
        for (int j = 0; j < 6; j++) g_acc[tid * 6 + j] = sq[tid * 6 + j];
        g_params[tid * 4 + 0] = sq[tid * 6 + 1] * inv;
        g_params[tid * 4 + 1] = sq[tid * 6 + 2] * inv;
        g_params[tid * 4 + 2] = expf(sq[tid * 6 + 3] * inv * 10.f);
        g_params[tid * 4 + 3] = expf(sq[tid * 6 + 4] * inv * 10.f);
    }
}

// ---------------------------------------------------------------- pass3: dist, hist, seed_fg (launch 4)
__global__ void __launch_bounds__(256) k_pass3(const float* __restrict__ pred,
                                               const int* __restrict__ cls_ids) {
    int b = blockIdx.x / BPB;
    int blk = blockIdx.x % BPB;

    __shared__ float sp[8][4];
    __shared__ int sch[8];
    if (threadIdx.x < 32) {
        int n = threadIdx.x / 4, k = threadIdx.x % 4;
        sp[n][k] = g_params[(b * 8 + n) * 4 + k];
    }
    if (threadIdx.x < 8) sch[threadIdx.x] = cls_ids[b * 8 + threadIdx.x];
    __syncthreads();

    float c0[8], c1[8], sx0[8], sx1[8];
    const __half* sdp[8];
#pragma unroll
    for (int n = 0; n < 8; n++) {
        c0[n] = sp[n][0]; c1[n] = sp[n][1];
        sx0[n] = sp[n][2]; sx1[n] = sp[n][3];
        sdp[n] = g_seeds + ((size_t)b * 8 + sch[n]) * HWx;
    }
    float fa[8] = {0,0,0,0,0,0,0,0};

    const float* pb = pred + (size_t)b * 12 * HWx;
    const unsigned* mbi = g_mbits + (size_t)b * HWx / 4;
    unsigned long long* hb = &g_hist[(size_t)(b * 8) * NBINS];

    for (int g = blk * 256 + threadIdx.x; g < HWx / 4; g += BPB * 256) {
        int hw = g * 4;
        int w = hw & (Wx - 1);
        int h = hw >> 10;
        float ybase = (float)h * (1.0f / 1023.0f);
        float4 p0 = *(const float4*)(pb + hw);
        float4 p1 = *(const float4*)(pb + HWx + hw);
        float e0[4], e1[4];
        e0[0] = tanh_approx(p0.x) + (float)(w + 0) * (2.0f / 2047.0f);
        e0[1] = tanh_approx(p0.y) + (float)(w + 1) * (2.0f / 2047.0f);
        e0[2] = tanh_approx(p0.z) + (float)(w + 2) * (2.0f / 2047.0f);
        e0[3] = tanh_approx(p0.w) + (float)(w + 3) * (2.0f / 2047.0f);
        e1[0] = tanh_approx(p1.x) + ybase;
        e1[1] = tanh_approx(p1.y) + ybase;
        e1[2] = tanh_approx(p1.z) + ybase;
        e1[3] = tanh_approx(p1.w) + ybase;
        unsigned bits = mbi[g];

#pragma unroll
        for (int n = 0; n < 8; n++) {
            uint2 svp = *(const uint2*)(sdp[n] + hw);
            __half2 hA = *reinterpret_cast<__half2*>(&svp.x);
            __half2 hB = *reinterpret_cast<__half2*>(&svp.y);
            float2 fA = __half22float2(hA);
            float2 fB = __half22float2(hB);
            float sv[4] = {fA.x, fA.y, fB.x, fB.y};
#pragma unroll
            for (int j = 0; j < 4; j++) {
                int lab = (bits >> (n + j * 8)) & 1;
                float labf = (float)lab;
                float dx = e0[j] - c0[n];
                float dy = e1[j] - c1[n];
                float d2 = fmaf(dx * dx, sx0[n], dy * dy * sx1[n]);
                float dist = __expf(-d2);
                float eb = fabsf(dist - labf) * (2.0f * BIN_SCALE);
                int bin = min((int)eb, NBINS - 1);
                atomicAdd(&hb[(size_t)n * NBINS + bin],
                          lab ? (1ull << 32) : 1ull);
                float dd = sv[j] - dist;
                if (lab) fa[n] = fmaf(dd, dd, fa[n]);
            }
        }
    }

    __shared__ float s_fg[8][8];
    int warp = threadIdx.x >> 5, lane = threadIdx.x & 31;
#pragma unroll
    for (int n = 0; n < 8; n++) {
        float v = wred(fa[n]);
        if (lane == 0) s_fg[n][warp] = v;
    }
    __syncthreads();
    if (threadIdx.x < 8) {
        float s = 0.f;
#pragma unroll
        for (int wv = 0; wv < 8; wv++) s += s_fg[threadIdx.x][wv];
        g_fg_part[(b * 8 + threadIdx.x) * 256 + blk] = s;
    }
}

// ---------------------------------------------------------------- Lovász scan, fp32 (launch 5)
__global__ void __launch_bounds__(1024) k_scan() {
    int seg = blockIdx.x;
    int tid = threadIdx.x;
    int warp = tid >> 5, lane = tid & 31;
    __shared__ unsigned long long wsum[32];
    __shared__ float rs[32];

    float Pf = g_acc[seg * 6 + 0];          // exact integer < 2^20
    unsigned carry_p = 0, carry_n = 0;
    float lov = 0.0f;
    const unsigned long long* hp = &g_hist[(size_t)seg * NBINS];

    for (int it = 0; it < NBINS / 1024; it++) {
        int bin = NBINS - 1 - (it * 1024 + tid);
        unsigned long long pair = hp[bin];
        unsigned nn = (unsigned)(pair & 0xffffffffu);
        unsigned np = (unsigned)(pair >> 32);
        unsigned long long inc = pair;
#pragma unroll
        for (int o = 1; o < 32; o <<= 1) {
            unsigned long long t = __shfl_up_sync(0xffffffffu, inc, o);
            if (lane >= o) inc += t;
        }
        if (lane == 31) wsum[warp] = inc;
        __syncthreads();
        if (warp == 0) {
            unsigned long long wv = wsum[lane];
#pragma unroll
            for (int o = 1; o < 32; o <<= 1) {
                unsigned long long t = __shfl_up_sync(0xffffffffu, wv, o);
                if (lane >= o) wv += t;
            }
            wsum[lane] = wv;
        }
        __syncthreads();
        unsigned long long incl = inc + (warp > 0 ? wsum[warp - 1] : 0ull);
        unsigned long long total = wsum[31];
        unsigned cp1 = carry_p + (unsigned)(incl >> 32);
        unsigned cn1 = carry_n + (unsigned)(incl & 0xffffffffu);
        unsigned cp0 = cp1 - np;
        unsigned cn0 = cn1 - nn;
        if (np | nn) {
            // jac = 1 - (P - cp)/(P + cn); all operands exact in fp32 (< 2^24)
            float j1 = 1.0f - __fdividef(Pf - (float)cp1, fmaxf(Pf + (float)cn1, 1.0f));
            float j0 = 1.0f - __fdividef(Pf - (float)cp0, fmaxf(Pf + (float)cn0, 1.0f));
            lov = fmaf(((float)bin + 0.5f) * (1.0f / 16384.0f), j1 - j0, lov);
        }
        carry_p += (unsigned)(total >> 32);
        carry_n += (unsigned)(total & 0xffffffffu);
        __syncthreads();
    }
    float lf = wred(lov);
    if (lane == 0) rs[warp] = lf;
    __syncthreads();
    if (tid < 32) {
        float v = wred(rs[tid]);
        if (tid == 0) g_lov[seg] = v;
    }
}

// ---------------------------------------------------------------- final (launch 6)
__global__ void __launch_bounds__(1024) k_final(const int* __restrict__ cls_ids,
                                                float* __restrict__ out) {
    __shared__ float s_fg[NSEG];
    __shared__ float s_bg[Bx];
    int warp = threadIdx.x >> 5, lane = threadIdx.x & 31;
    if (warp < NSEG) {
        float v = 0.f;
#pragma unroll
        for (int i = 0; i < 8; i++) v += g_fg_part[warp * 256 + lane + i * 32];
        v = wred(v);
        if (lane == 0) s_fg[warp] = v;
    } else if (warp < NSEG + Bx) {
        int b = warp - NSEG;
        float v = 0.f;
#pragma unroll
        for (int i = 0; i < 8; i++) v += g_bg_part[b * 256 + lane + i * 32];
        v = wred(v);
        if (lane == 0) s_bg[b] = v;
    }
    __syncthreads();
    if (threadIdx.x == 0) {
        float total = 0.f;
        for (int b = 0; b < Bx; b++) {
            float obj = 0.f, inst = 0.f, var = 0.f, fg = 0.f;
            for (int n = 0; n < 8; n++) {
                int seg = b * 8 + n;
                float cnt = g_acc[seg * 6 + 0];
                float valid = (cnt >= MINPIX) ? 1.f : 0.f;
                float cs = fmaxf(cnt, 1.f);
                float S0 = g_acc[seg * 6 + 3];
                float S1 = g_acc[seg * 6 + 4];
                float Q  = g_acc[seg * 6 + 5];
                float vi = (Q - (S0 * S0 + S1 * S1) / cs) / (2.f * cs);
                obj += valid;
                inst += g_lov[seg] * valid;
                var += vi * valid;
                fg += FGW[cls_ids[seg]] * s_fg[seg] * valid;
            }
            float os = fmaxf(obj, 1.f);
            float seed_l = (s_bg[b] + fg) * (1.0f / (float)HWx);
            total += inst / os + 10.f * (var / os) + seed_l;
        }
        out[0] = total * 0.5f;
    }
}

// ---------------------------------------------------------------- launch
extern "C" void kernel_launch(void* const* d_in, const int* in_sizes, int n_in,
                              void* d_out, int out_size) {
    const float* pred = (const float*)d_in[0];
    const int* bbox   = (const int*)d_in[1];
    const int* masks  = (const int*)d_in[2];
    const int* cls    = (const int*)d_in[3];
    (void)in_sizes; (void)n_in; (void)out_size;

    k_seed<<<Bx * BPB, 256>>>(pred, bbox);        // 0 (also zeroes hist)
    k_bits<<<Bx * BPB, 256>>>(masks);             // 1
    k_accum<<<Bx * BPB, 256>>>(pred);             // 2
    k_params<<<1, 1024>>>();                      // 3 <- profiled (known-small)
    k_pass3<<<Bx * BPB, 256>>>(pred, cls);        // 4
    k_scan<<<NSEG, 1024>>>();                     // 5
    k_final<<<1, 1024>>>(cls, (float*)d_out);     // 6
}

// round 11
// speedup vs baseline: 7.4323x; 1.1617x over previous
#include <cuda_runtime.h>
#include <cuda_fp16.h>

#define Bx     2
#define Hx     512
#define Wx     1024
#define HWx    (Hx * Wx)          // 524288
#define NSEG   16
#define NBINS  8192
#define BIN_SCALE 4096.0f
#define MINPIX 128.0f
#define BPB    256                // blocks per batch for big passes

// ---- globals ----
// u32 counts, layout [seg][bin][{neg,pos}] so scan reads one u64 per bin (low=neg, high=pos)
__device__ __align__(16) unsigned g_hist32[NSEG * NBINS * 2];   // 1 MB
__device__ __align__(16) float g_acc[NSEG * 6];        // cnt, Se0, Se1, Ss0, Ss1, Q
__device__ __align__(16) float g_lov[NSEG];
__device__ __align__(16) float g_params[NSEG * 4];     // c0 c1 sx0 sx1
// per-block partials (fully overwritten each run; no zeroing needed)
__device__ __align__(16) float g_acc_part[96 * 256];   // [q][blk] q=(b*8+n)*6+j
__device__ __align__(16) float g_bg_part[2 * 256];     // [b][blk]
__device__ __align__(16) float g_fg_part[NSEG * 256];  // [seg][blk]
// scratch
__device__ __align__(16) __half g_seeds[Bx * 8 * HWx];       // [b][c][hw]
__device__ __align__(16) unsigned g_mbits[Bx * HWx / 4];     // byte j: bit n = mask n

__device__ const float FGW[8] = {10.0f, 10.0f, 10.0f, 40.0f, 80.0f, 100.0f, 60.0f, 20.0f};

__device__ __forceinline__ float wred(float v) {
    v += __shfl_down_sync(0xffffffffu, v, 16);
    v += __shfl_down_sync(0xffffffffu, v, 8);
    v += __shfl_down_sync(0xffffffffu, v, 4);
    v += __shfl_down_sync(0xffffffffu, v, 2);
    v += __shfl_down_sync(0xffffffffu, v, 1);
    return v;
}

__device__ __forceinline__ float tanh_approx(float x) {
    float r;
    asm("tanh.approx.f32 %0, %1;" : "=f"(r) : "f"(x));
    return r;
}
__device__ __forceinline__ __half2 sigmoid2_h(float a, float b) {
    __half2 x = __floats2half2_rn(0.5f * a, 0.5f * b);
    __half2 t;
    asm("tanh.approx.f16x2 %0, %1;" : "=r"(*(unsigned*)&t) : "r"(*(unsigned*)&x));
    const __half2 half2_half = __floats2half2_rn(0.5f, 0.5f);
    return __hfma2(t, half2_half, half2_half);
}

// ---------------------------------------------------------------- k_seed: ch4-11 + bbox, zeroes hist (launch 0)
__global__ void __launch_bounds__(256, 4) k_seed(const float* __restrict__ pred,
                                                 const int* __restrict__ bbox) {
    int b = blockIdx.x / BPB;
    int blk = blockIdx.x % BPB;
    const float* pb = pred + (size_t)b * 12 * HWx;
    const int* bbb = bbox + (size_t)b * 9 * HWx;
    __half* sdo = g_seeds + (size_t)b * 8 * HWx;

    // zero the histogram (1MB = 65536 float4s over 512x256 threads)
    {
        int base = blockIdx.x * 256 + threadIdx.x;
        if (base < NSEG * NBINS * 2 / 4)
            reinterpret_cast<float4*>(g_hist32)[base] = make_float4(0.f, 0.f, 0.f, 0.f);
    }

    float bg = 0.f;
    for (int g = blk * 256 + threadIdx.x; g < HWx / 4; g += BPB * 256) {
        int hw = g * 4;
#pragma unroll
        for (int c = 0; c < 8; c++) {
            float4 sv = *(const float4*)(pb + (size_t)(4 + c) * HWx + hw);
            int4 bv = *(const int4*)(bbb + (size_t)(1 + c) * HWx + hw);
            __half2 s01 = sigmoid2_h(sv.x, sv.y);
            __half2 s23 = sigmoid2_h(sv.z, sv.w);
            float2 f01 = __half22float2(s01);
            float2 f23 = __half22float2(s23);
            if (bv.x == 0) bg = fmaf(f01.x, f01.x, bg);
            if (bv.y == 0) bg = fmaf(f01.y, f01.y, bg);
            if (bv.z == 0) bg = fmaf(f23.x, f23.x, bg);
            if (bv.w == 0) bg = fmaf(f23.y, f23.y, bg);
            uint2 pk;
            pk.x = *reinterpret_cast<unsigned*>(&s01);
            pk.y = *reinterpret_cast<unsigned*>(&s23);
            *(uint2*)(sdo + (size_t)c * HWx + hw) = pk;
        }
    }
    __shared__ float s_bg[8];
    int warp = threadIdx.x >> 5, lane = threadIdx.x & 31;
    bg = wred(bg);
    if (lane == 0) s_bg[warp] = bg;
    __syncthreads();
    if (threadIdx.x == 0) {
        float s = 0.f;
#pragma unroll
        for (int wv = 0; wv < 8; wv++) s += s_bg[wv];
        g_bg_part[b * 256 + blk] = s;
    }
}

// ---------------------------------------------------------------- k_maskaccum: masks + ch0-3 -> mbits + sums (launch 1)
__global__ void __launch_bounds__(256) k_maskaccum(const float* __restrict__ pred,
                                                   const int* __restrict__ masks) {
    int b = blockIdx.x / BPB;
    int blk = blockIdx.x % BPB;
    const float* pb = pred + (size_t)b * 12 * HWx;
    const int* mb  = masks + (size_t)b * 8 * HWx;
    unsigned* mbo = g_mbits + (size_t)b * HWx / 4;

    float acc[8][5];   // Se0, Se1, Ss0, Ss1, Q
    int cnt[8];
#pragma unroll
    for (int n = 0; n < 8; n++) {
        cnt[n] = 0;
#pragma unroll
        for (int j = 0; j < 5; j++) acc[n][j] = 0.f;
    }

    for (int g = blk * 256 + threadIdx.x; g < HWx / 4; g += BPB * 256) {
        int hw = g * 4;
        int w = hw & (Wx - 1);
        int h = hw >> 10;
        float ybase = (float)h * (1.0f / 1023.0f);

        // build mask bits
        unsigned bits = 0;
#pragma unroll
        for (int n = 0; n < 8; n++) {
            int4 mv = *(const int4*)(mb + (size_t)n * HWx + hw);
            if (mv.x > 0) bits |= (1u << (n + 0));
            if (mv.y > 0) bits |= (1u << (n + 8));
            if (mv.z > 0) bits |= (1u << (n + 16));
            if (mv.w > 0) bits |= (1u << (n + 24));
        }
        mbo[g] = bits;

        float4 p0 = *(const float4*)(pb + hw);
        float4 p1 = *(const float4*)(pb + HWx + hw);
        float4 s0v = *(const float4*)(pb + 2 * HWx + hw);
        float4 s1v = *(const float4*)(pb + 3 * HWx + hw);

        float e0[4], e1[4];
        e0[0] = tanh_approx(p0.x) + (float)(w + 0) * (2.0f / 2047.0f);
        e0[1] = tanh_approx(p0.y) + (float)(w + 1) * (2.0f / 2047.0f);
        e0[2] = tanh_approx(p0.z) + (float)(w + 2) * (2.0f / 2047.0f);
        e0[3] = tanh_approx(p0.w) + (float)(w + 3) * (2.0f / 2047.0f);
        e1[0] = tanh_approx(p1.x) + ybase;
        e1[1] = tanh_approx(p1.y) + ybase;
        e1[2] = tanh_approx(p1.z) + ybase;
        e1[3] = tanh_approx(p1.w) + ybase;
        float sg0[4] = {s0v.x, s0v.y, s0v.z, s0v.w};
        float sg1[4] = {s1v.x, s1v.y, s1v.z, s1v.w};
        float q4[4];
#pragma unroll
        for (int j = 0; j < 4; j++) q4[j] = fmaf(sg0[j], sg0[j], sg1[j] * sg1[j]);

#pragma unroll
        for (int n = 0; n < 8; n++) {
            cnt[n] += __popc(bits & (0x01010101u << n));
#pragma unroll
            for (int j = 0; j < 4; j++) {
                if ((bits >> (n + j * 8)) & 1u) {
                    acc[n][0] += e0[j];
                    acc[n][1] += e1[j];
                    acc[n][2] += sg0[j];
                    acc[n][3] += sg1[j];
                    acc[n][4] += q4[j];
                }
            }
        }
    }

    __shared__ float s_red[48][8];
    int warp = threadIdx.x >> 5, lane = threadIdx.x & 31;
#pragma unroll
    for (int n = 0; n < 8; n++) {
        float v;
        v = wred((float)cnt[n]); if (lane == 0) s_red[n * 6 + 0][warp] = v;
#pragma unroll
        for (int j = 0; j < 5; j++) {
            v = wred(acc[n][j]);
            if (lane == 0) s_red[n * 6 + 1 + j][warp] = v;
        }
    }
    __syncthreads();
    if (threadIdx.x < 48) {
        float s = 0.f;
#pragma unroll
        for (int wv = 0; wv < 8; wv++) s += s_red[threadIdx.x][wv];
        int q = (b * 8 + (threadIdx.x / 6)) * 6 + (threadIdx.x % 6);
        g_acc_part[q * 256 + blk] = s;
    }
}

// ---------------------------------------------------------------- k_params: reduce partials (launch 2)
__global__ void __launch_bounds__(1024) k_params() {
    __shared__ float sq[96];
    int warp = threadIdx.x >> 5, lane = threadIdx.x & 31;
    for (int q = warp; q < 96; q += 32) {
        float v = 0.f;
#pragma unroll
        for (int i = 0; i < 8; i++) v += g_acc_part[q * 256 + lane + i * 32];
        v = wred(v);
        if (lane == 0) sq[q] = v;
    }
    __syncthreads();
    int tid = threadIdx.x;
    if (tid < NSEG) {
        float cnt = sq[tid * 6 + 0];
        float cs = fmaxf(cnt, 1.f);
        float inv = 1.f / cs;
#pragma unroll
        for (int j = 0; j < 6; j++) g_acc[tid * 6 + j] = sq[tid * 6 + j];
        g_params[tid * 4 + 0] = sq[tid * 6 + 1] * inv;
        g_params[tid * 4 + 1] = sq[tid * 6 + 2] * inv;
        g_params[tid * 4 + 2] = expf(sq[tid * 6 + 3] * inv * 10.f);
        g_params[tid * 4 + 3] = expf(sq[tid * 6 + 4] * inv * 10.f);
    }
}

// ---------------------------------------------------------------- pass3: dist, hist, seed_fg (launch 3 <- profiled)
__global__ void __launch_bounds__(256) k_pass3(const float* __restrict__ pred,
                                               const int* __restrict__ cls_ids) {
    int b = blockIdx.x / BPB;
    int blk = blockIdx.x % BPB;

    __shared__ float sp[8][4];
    __shared__ int sch[8];
    if (threadIdx.x < 32) {
        int n = threadIdx.x / 4, k = threadIdx.x % 4;
        sp[n][k] = g_params[(b * 8 + n) * 4 + k];
    }
    if (threadIdx.x < 8) sch[threadIdx.x] = cls_ids[b * 8 + threadIdx.x];
    __syncthreads();

    float c0[8], c1[8], sx0[8], sx1[8];
    const __half* sdp[8];
#pragma unroll
    for (int n = 0; n < 8; n++) {
        c0[n] = sp[n][0]; c1[n] = sp[n][1];
        sx0[n] = sp[n][2]; sx1[n] = sp[n][3];
        sdp[n] = g_seeds + ((size_t)b * 8 + sch[n]) * HWx;
    }
    float fa[8] = {0,0,0,0,0,0,0,0};

    const float* pb = pred + (size_t)b * 12 * HWx;
    const unsigned* mbi = g_mbits + (size_t)b * HWx / 4;
    unsigned* hb = g_hist32 + (size_t)(b * 8) * NBINS * 2;

    for (int g = blk * 256 + threadIdx.x; g < HWx / 4; g += BPB * 256) {
        int hw = g * 4;
        int w = hw & (Wx - 1);
        int h = hw >> 10;
        float ybase = (float)h * (1.0f / 1023.0f);
        float4 p0 = *(const float4*)(pb + hw);
        float4 p1 = *(const float4*)(pb + HWx + hw);
        float e0[4], e1[4];
        e0[0] = tanh_approx(p0.x) + (float)(w + 0) * (2.0f / 2047.0f);
        e0[1] = tanh_approx(p0.y) + (float)(w + 1) * (2.0f / 2047.0f);
        e0[2] = tanh_approx(p0.z) + (float)(w + 2) * (2.0f / 2047.0f);
        e0[3] = tanh_approx(p0.w) + (float)(w + 3) * (2.0f / 2047.0f);
        e1[0] = tanh_approx(p1.x) + ybase;
        e1[1] = tanh_approx(p1.y) + ybase;
        e1[2] = tanh_approx(p1.z) + ybase;
        e1[3] = tanh_approx(p1.w) + ybase;
        unsigned bits = mbi[g];

#pragma unroll
        for (int n = 0; n < 8; n++) {
            uint2 svp = *(const uint2*)(sdp[n] + hw);
            __half2 hA = *reinterpret_cast<__half2*>(&svp.x);
            __half2 hB = *reinterpret_cast<__half2*>(&svp.y);
            float2 fA = __half22float2(hA);
            float2 fB = __half22float2(hB);
            float sv[4] = {fA.x, fA.y, fB.x, fB.y};
#pragma unroll
            for (int j = 0; j < 4; j++) {
                int lab = (bits >> (n + j * 8)) & 1;
                float labf = (float)lab;
                float dx = e0[j] - c0[n];
                float dy = e1[j] - c1[n];
                float d2 = fmaf(dx * dx, sx0[n], dy * dy * sx1[n]);
                float dist = __expf(-d2);
                float eb = fabsf(dist - labf) * (2.0f * BIN_SCALE);
                int bin = min((int)eb, NBINS - 1);
                atomicAdd(&hb[((size_t)n * NBINS + bin) * 2 + lab], 1u);
                float dd = sv[j] - dist;
                if (lab) fa[n] = fmaf(dd, dd, fa[n]);
            }
        }
    }

    __shared__ float s_fg[8][8];
    int warp = threadIdx.x >> 5, lane = threadIdx.x & 31;
#pragma unroll
    for (int n = 0; n < 8; n++) {
        float v = wred(fa[n]);
        if (lane == 0) s_fg[n][warp] = v;
    }
    __syncthreads();
    if (threadIdx.x < 8) {
        float s = 0.f;
#pragma unroll
        for (int wv = 0; wv < 8; wv++) s += s_fg[threadIdx.x][wv];
        g_fg_part[(b * 8 + threadIdx.x) * 256 + blk] = s;
    }
}

// ---------------------------------------------------------------- Lovász scan, fp32 (launch 4)
__global__ void __launch_bounds__(1024) k_scan() {
    int seg = blockIdx.x;
    int tid = threadIdx.x;
    int warp = tid >> 5, lane = tid & 31;
    __shared__ unsigned long long wsum[32];
    __shared__ float rs[32];

    float Pf = g_acc[seg * 6 + 0];          // exact integer < 2^20
    unsigned carry_p = 0, carry_n = 0;
    float lov = 0.0f;
    const unsigned long long* hp =
        reinterpret_cast<const unsigned long long*>(g_hist32) + (size_t)seg * NBINS;

    for (int it = 0; it < NBINS / 1024; it++) {
        int bin = NBINS - 1 - (it * 1024 + tid);
        unsigned long long pair = hp[bin];      // low=neg, high=pos
        unsigned nn = (unsigned)(pair & 0xffffffffu);
        unsigned np = (unsigned)(pair >> 32);
        unsigned long long inc = pair;
#pragma unroll
        for (int o = 1; o < 32; o <<= 1) {
            unsigned long long t = __shfl_up_sync(0xffffffffu, inc, o);
            if (lane >= o) inc += t;
        }
        if (lane == 31) wsum[warp] = inc;
        __syncthreads();
        if (warp == 0) {
            unsigned long long wv = wsum[lane];
#pragma unroll
            for (int o = 1; o < 32; o <<= 1) {
                unsigned long long t = __shfl_up_sync(0xffffffffu, wv, o);
                if (lane >= o) wv += t;
            }
            wsum[lane] = wv;
        }
        __syncthreads();
        unsigned long long incl = inc + (warp > 0 ? wsum[warp - 1] : 0ull);
        unsigned long long total = wsum[31];
        unsigned cp1 = carry_p + (unsigned)(incl >> 32);
        unsigned cn1 = carry_n + (unsigned)(incl & 0xffffffffu);
        unsigned cp0 = cp1 - np;
        unsigned cn0 = cn1 - nn;
        if (np | nn) {
            float j1 = 1.0f - __fdividef(Pf - (float)cp1, fmaxf(Pf + (float)cn1, 1.0f));
            float j0 = 1.0f - __fdividef(Pf - (float)cp0, fmaxf(Pf + (float)cn0, 1.0f));
            lov = fmaf(((float)bin + 0.5f) * (1.0f / BIN_SCALE), j1 - j0, lov);
        }
        carry_p += (unsigned)(total >> 32);
        carry_n += (unsigned)(total & 0xffffffffu);
        __syncthreads();
    }
    float lf = wred(lov);
    if (lane == 0) rs[warp] = lf;
    __syncthreads();
    if (tid < 32) {
        float v = wred(rs[tid]);
        if (tid == 0) g_lov[seg] = v;
    }
}

// ---------------------------------------------------------------- final (launch 5)
__global__ void __launch_bounds__(1024) k_final(const int* __restrict__ cls_ids,
                                                float* __restrict__ out) {
    __shared__ float s_fg[NSEG];
    __shared__ float s_bg[Bx];
    int warp = threadIdx.x >> 5, lane = threadIdx.x & 31;
    if (warp < NSEG) {
        float v = 0.f;
#pragma unroll
        for (int i = 0; i < 8; i++) v += g_fg_part[warp * 256 + lane + i * 32];
        v = wred(v);
        if (lane == 0) s_fg[warp] = v;
    } else if (warp < NSEG + Bx) {
        int b = warp - NSEG;
        float v = 0.f;
#pragma unroll
        for (int i = 0; i < 8; i++) v += g_bg_part[b * 256 + lane + i * 32];
        v = wred(v);
        if (lane == 0) s_bg[b] = v;
    }
    __syncthreads();
    if (threadIdx.x == 0) {
        float total = 0.f;
        for (int b = 0; b < Bx; b++) {
            float obj = 0.f, inst = 0.f, var = 0.f, fg = 0.f;
            for (int n = 0; n < 8; n++) {
                int seg = b * 8 + n;
                float cnt = g_acc[seg * 6 + 0];
                float valid = (cnt >= MINPIX) ? 1.f : 0.f;
                float cs = fmaxf(cnt, 1.f);
                float S0 = g_acc[seg * 6 + 3];
                float S1 = g_acc[seg * 6 + 4];
                float Q  = g_acc[seg * 6 + 5];
                float vi = (Q - (S0 * S0 + S1 * S1) / cs) / (2.f * cs);
                obj += valid;
                inst += g_lov[seg] * valid;
                var += vi * valid;
                fg += FGW[cls_ids[seg]] * s_fg[seg] * valid;
            }
            float os = fmaxf(obj, 1.f);
            float seed_l = (s_bg[b] + fg) * (1.0f / (float)HWx);
            total += inst / os + 10.f * (var / os) + seed_l;
        }
        out[0] = total * 0.5f;
    }
}

// ---------------------------------------------------------------- launch
extern "C" void kernel_launch(void* const* d_in, const int* in_sizes, int n_in,
                              void* d_out, int out_size) {
    const float* pred = (const float*)d_in[0];
    const int* bbox   = (const int*)d_in[1];
    const int* masks  = (const int*)d_in[2];
    const int* cls    = (const int*)d_in[3];
    (void)in_sizes; (void)n_in; (void)out_size;

    k_seed<<<Bx * BPB, 256>>>(pred, bbox);          // 0 (also zeroes hist)
    k_maskaccum<<<Bx * BPB, 256>>>(pred, masks);    // 1
    k_params<<<1, 1024>>>();                        // 2
    k_pass3<<<Bx * BPB, 256>>>(pred, cls);          // 3 <- profiled
    k_scan<<<NSEG, 1024>>>();                       // 4
    k_final<<<1, 1024>>>(cls, (float*)d_out);       // 5
}

// round 12
// speedup vs baseline: 7.7021x; 1.0363x over previous
#include <cuda_runtime.h>
#include <cuda_fp16.h>

#define Bx     2
#define Hx     512
#define Wx     1024
#define HWx    (Hx * Wx)          // 524288
#define NSEG   16
#define NBINS  8192
#define BIN_SCALE 4096.0f
#define MINPIX 128.0f
#define BPB    256                // blocks per batch for big passes

// ---- globals ----
// u32 counts, layout [seg][bin][{neg,pos}] so scan reads one u64 per bin (low=neg, high=pos)
__device__ __align__(16) unsigned g_hist32[NSEG * NBINS * 2];   // 1 MB
__device__ __align__(16) float g_acc[NSEG * 6];        // cnt, Se0, Se1, Ss0, Ss1, Q
__device__ __align__(16) float g_lov[NSEG];
__device__ __align__(16) float g_params[NSEG * 4];     // c0 c1 sx0 sx1
// per-block partials (fully overwritten each run; no zeroing needed)
__device__ __align__(16) float g_acc_part[96 * 256];   // [q][blk] q=(b*8+n)*6+j
__device__ __align__(16) float g_bg_part[2 * 256];     // [b][blk]
__device__ __align__(16) float g_fg_part[NSEG * 256];  // [seg][blk]
// scratch
__device__ __align__(16) __half g_seeds[Bx * 8 * HWx];       // [b][c][hw]
__device__ __align__(16) unsigned g_mbits[Bx * HWx / 4];     // byte j: bit n = mask n

__device__ const float FGW[8] = {10.0f, 10.0f, 10.0f, 40.0f, 80.0f, 100.0f, 60.0f, 20.0f};

__device__ __forceinline__ float wred(float v) {
    v += __shfl_down_sync(0xffffffffu, v, 16);
    v += __shfl_down_sync(0xffffffffu, v, 8);
    v += __shfl_down_sync(0xffffffffu, v, 4);
    v += __shfl_down_sync(0xffffffffu, v, 2);
    v += __shfl_down_sync(0xffffffffu, v, 1);
    return v;
}

__device__ __forceinline__ float tanh_approx(float x) {
    float r;
    asm("tanh.approx.f32 %0, %1;" : "=f"(r) : "f"(x));
    return r;
}
__device__ __forceinline__ __half2 sigmoid2_h(float a, float b) {
    __half2 x = __floats2half2_rn(0.5f * a, 0.5f * b);
    __half2 t;
    asm("tanh.approx.f16x2 %0, %1;" : "=r"(*(unsigned*)&t) : "r"(*(unsigned*)&x));
    const __half2 half2_half = __floats2half2_rn(0.5f, 0.5f);
    return __hfma2(t, half2_half, half2_half);
}

// ---------------------------------------------------------------- k_seed: ch4-11 + bbox, zeroes hist (launch 0)
__global__ void __launch_bounds__(256, 4) k_seed(const float* __restrict__ pred,
                                                 const int* __restrict__ bbox) {
    int b = blockIdx.x / BPB;
    int blk = blockIdx.x % BPB;
    const float* pb = pred + (size_t)b * 12 * HWx;
    const int* bbb = bbox + (size_t)b * 9 * HWx;
    __half* sdo = g_seeds + (size_t)b * 8 * HWx;

    // zero the histogram (1MB = 65536 float4s over 512x256 threads)
    {
        int base = blockIdx.x * 256 + threadIdx.x;
        if (base < NSEG * NBINS * 2 / 4)
            reinterpret_cast<float4*>(g_hist32)[base] = make_float4(0.f, 0.f, 0.f, 0.f);
    }

    float bg = 0.f;
    for (int g = blk * 256 + threadIdx.x; g < HWx / 4; g += BPB * 256) {
        int hw = g * 4;
#pragma unroll
        for (int c = 0; c < 8; c++) {
            float4 sv = *(const float4*)(pb + (size_t)(4 + c) * HWx + hw);
            int4 bv = *(const int4*)(bbb + (size_t)(1 + c) * HWx + hw);
            __half2 s01 = sigmoid2_h(sv.x, sv.y);
            __half2 s23 = sigmoid2_h(sv.z, sv.w);
            float2 f01 = __half22float2(s01);
            float2 f23 = __half22float2(s23);
            if (bv.x == 0) bg = fmaf(f01.x, f01.x, bg);
            if (bv.y == 0) bg = fmaf(f01.y, f01.y, bg);
            if (bv.z == 0) bg = fmaf(f23.x, f23.x, bg);
            if (bv.w == 0) bg = fmaf(f23.y, f23.y, bg);
            uint2 pk;
            pk.x = *reinterpret_cast<unsigned*>(&s01);
            pk.y = *reinterpret_cast<unsigned*>(&s23);
            *(uint2*)(sdo + (size_t)c * HWx + hw) = pk;
        }
    }
    __shared__ float s_bg[8];
    int warp = threadIdx.x >> 5, lane = threadIdx.x & 31;
    bg = wred(bg);
    if (lane == 0) s_bg[warp] = bg;
    __syncthreads();
    if (threadIdx.x == 0) {
        float s = 0.f;
#pragma unroll
        for (int wv = 0; wv < 8; wv++) s += s_bg[wv];
        g_bg_part[b * 256 + blk] = s;
    }
}

// ---------------------------------------------------------------- k_maskaccum: masks + ch0-3 -> mbits + sums (launch 1)
__global__ void __launch_bounds__(256) k_maskaccum(const float* __restrict__ pred,
                                                   const int* __restrict__ masks) {
    int b = blockIdx.x / BPB;
    int blk = blockIdx.x % BPB;
    const float* pb = pred + (size_t)b * 12 * HWx;
    const int* mb  = masks + (size_t)b * 8 * HWx;
    unsigned* mbo = g_mbits + (size_t)b * HWx / 4;

    float acc[8][5];   // Se0, Se1, Ss0, Ss1, Q
    int cnt[8];
#pragma unroll
    for (int n = 0; n < 8; n++) {
        cnt[n] = 0;
#pragma unroll
        for (int j = 0; j < 5; j++) acc[n][j] = 0.f;
    }

    for (int g = blk * 256 + threadIdx.x; g < HWx / 4; g += BPB * 256) {
        int hw = g * 4;
        int w = hw & (Wx - 1);
        int h = hw >> 10;
        float ybase = (float)h * (1.0f / 1023.0f);

        unsigned bits = 0;
#pragma unroll
        for (int n = 0; n < 8; n++) {
            int4 mv = *(const int4*)(mb + (size_t)n * HWx + hw);
            if (mv.x > 0) bits |= (1u << (n + 0));
            if (mv.y > 0) bits |= (1u << (n + 8));
            if (mv.z > 0) bits |= (1u << (n + 16));
            if (mv.w > 0) bits |= (1u << (n + 24));
        }
        mbo[g] = bits;

        float4 p0 = *(const float4*)(pb + hw);
        float4 p1 = *(const float4*)(pb + HWx + hw);
        float4 s0v = *(const float4*)(pb + 2 * HWx + hw);
        float4 s1v = *(const float4*)(pb + 3 * HWx + hw);

        float e0[4], e1[4];
        e0[0] = tanh_approx(p0.x) + (float)(w + 0) * (2.0f / 2047.0f);
        e0[1] = tanh_approx(p0.y) + (float)(w + 1) * (2.0f / 2047.0f);
        e0[2] = tanh_approx(p0.z) + (float)(w + 2) * (2.0f / 2047.0f);
        e0[3] = tanh_approx(p0.w) + (float)(w + 3) * (2.0f / 2047.0f);
        e1[0] = tanh_approx(p1.x) + ybase;
        e1[1] = tanh_approx(p1.y) + ybase;
        e1[2] = tanh_approx(p1.z) + ybase;
        e1[3] = tanh_approx(p1.w) + ybase;
        float sg0[4] = {s0v.x, s0v.y, s0v.z, s0v.w};
        float sg1[4] = {s1v.x, s1v.y, s1v.z, s1v.w};
        float q4[4];
#pragma unroll
        for (int j = 0; j < 4; j++) q4[j] = fmaf(sg0[j], sg0[j], sg1[j] * sg1[j]);

#pragma unroll
        for (int n = 0; n < 8; n++) {
            cnt[n] += __popc(bits & (0x01010101u << n));
#pragma unroll
            for (int j = 0; j < 4; j++) {
                if ((bits >> (n + j * 8)) & 1u) {
                    acc[n][0] += e0[j];
                    acc[n][1] += e1[j];
                    acc[n][2] += sg0[j];
                    acc[n][3] += sg1[j];
                    acc[n][4] += q4[j];
                }
            }
        }
    }

    __shared__ float s_red[48][8];
    int warp = threadIdx.x >> 5, lane = threadIdx.x & 31;
#pragma unroll
    for (int n = 0; n < 8; n++) {
        float v;
        v = wred((float)cnt[n]); if (lane == 0) s_red[n * 6 + 0][warp] = v;
#pragma unroll
        for (int j = 0; j < 5; j++) {
            v = wred(acc[n][j]);
            if (lane == 0) s_red[n * 6 + 1 + j][warp] = v;
        }
    }
    __syncthreads();
    if (threadIdx.x < 48) {
        float s = 0.f;
#pragma unroll
        for (int wv = 0; wv < 8; wv++) s += s_red[threadIdx.x][wv];
        int q = (b * 8 + (threadIdx.x / 6)) * 6 + (threadIdx.x % 6);
        g_acc_part[q * 256 + blk] = s;
    }
}

// ---------------------------------------------------------------- k_params: reduce partials (launch 2)
__global__ void __launch_bounds__(1024) k_params() {
    __shared__ float sq[96];
    int warp = threadIdx.x >> 5, lane = threadIdx.x & 31;
    for (int q = warp; q < 96; q += 32) {
        float v = 0.f;
#pragma unroll
        for (int i = 0; i < 8; i++) v += g_acc_part[q * 256 + lane + i * 32];
        v = wred(v);
        if (lane == 0) sq[q] = v;
    }
    __syncthreads();
    int tid = threadIdx.x;
    if (tid < NSEG) {
        float cnt = sq[tid * 6 + 0];
        float cs = fmaxf(cnt, 1.f);
        float inv = 1.f / cs;
#pragma unroll
        for (int j = 0; j < 6; j++) g_acc[tid * 6 + j] = sq[tid * 6 + j];
        g_params[tid * 4 + 0] = sq[tid * 6 + 1] * inv;
        g_params[tid * 4 + 1] = sq[tid * 6 + 2] * inv;
        g_params[tid * 4 + 2] = expf(sq[tid * 6 + 3] * inv * 10.f);
        g_params[tid * 4 + 3] = expf(sq[tid * 6 + 4] * inv * 10.f);
    }
}

// ---------------------------------------------------------------- pass3: dist, hist, seed_fg (launch 3 <- profiled)
__global__ void __launch_bounds__(256, 2) k_pass3(const float* __restrict__ pred,
                                                  const int* __restrict__ cls_ids) {
    int b = blockIdx.x / BPB;
    int blk = blockIdx.x % BPB;

    __shared__ float sp[8][4];
    __shared__ int sch[8];
    if (threadIdx.x < 32) {
        int n = threadIdx.x / 4, k = threadIdx.x % 4;
        sp[n][k] = g_params[(b * 8 + n) * 4 + k];
    }
    if (threadIdx.x < 8) sch[threadIdx.x] = cls_ids[b * 8 + threadIdx.x];
    __syncthreads();

    float c0[8], c1[8], sx0[8], sx1[8];
    unsigned soff[8];                      // element offsets, one base pointer
    const __half* sbase = g_seeds + (size_t)b * 8 * HWx;
#pragma unroll
    for (int n = 0; n < 8; n++) {
        c0[n] = sp[n][0]; c1[n] = sp[n][1];
        sx0[n] = sp[n][2]; sx1[n] = sp[n][3];
        soff[n] = (unsigned)sch[n] * HWx;
    }
    float fa[8] = {0,0,0,0,0,0,0,0};

    const float* pb = pred + (size_t)b * 12 * HWx;
    const unsigned* mbi = g_mbits + (size_t)b * HWx / 4;
    unsigned* hb = g_hist32 + (size_t)(b * 8) * NBINS * 2;

    for (int g = blk * 256 + threadIdx.x; g < HWx / 4; g += BPB * 256) {
        int hw = g * 4;
        int w = hw & (Wx - 1);
        int h = hw >> 10;
        float ybase = (float)h * (1.0f / 1023.0f);
        float4 p0 = *(const float4*)(pb + hw);
        float4 p1 = *(const float4*)(pb + HWx + hw);
        float e0[4], e1[4];
        e0[0] = tanh_approx(p0.x) + (float)(w + 0) * (2.0f / 2047.0f);
        e0[1] = tanh_approx(p0.y) + (float)(w + 1) * (2.0f / 2047.0f);
        e0[2] = tanh_approx(p0.z) + (float)(w + 2) * (2.0f / 2047.0f);
        e0[3] = tanh_approx(p0.w) + (float)(w + 3) * (2.0f / 2047.0f);
        e1[0] = tanh_approx(p1.x) + ybase;
        e1[1] = tanh_approx(p1.y) + ybase;
        e1[2] = tanh_approx(p1.z) + ybase;
        e1[3] = tanh_approx(p1.w) + ybase;
        unsigned bits = mbi[g];

#pragma unroll
        for (int n = 0; n < 8; n++) {
            uint2 svp = *(const uint2*)(sbase + soff[n] + hw);
            __half2 hA = *reinterpret_cast<__half2*>(&svp.x);
            __half2 hB = *reinterpret_cast<__half2*>(&svp.y);
            float2 fA = __half22float2(hA);
            float2 fB = __half22float2(hB);
            float sv[4] = {fA.x, fA.y, fB.x, fB.y};
#pragma unroll
            for (int j = 0; j < 4; j++) {
                unsigned lab = (bits >> (n + j * 8)) & 1u;
                float mf = (float)lab;
                float dx = e0[j] - c0[n];
                float dy = e1[j] - c1[n];
                float d2 = fmaf(dx * dx, sx0[n], dy * dy * sx1[n]);
                float dist = __expf(-d2);
                float eb = fabsf(dist - mf) * (2.0f * BIN_SCALE);
                int bin = min((int)eb, NBINS - 1);
                atomicAdd(&hb[((size_t)n * NBINS + bin) * 2 + lab], 1u);
                float dd = sv[j] - dist;
                fa[n] = fmaf(mf * dd, dd, fa[n]);
            }
        }
    }

    __shared__ float s_fg[8][8];
    int warp = threadIdx.x >> 5, lane = threadIdx.x & 31;
#pragma unroll
    for (int n = 0; n < 8; n++) {
        float v = wred(fa[n]);
        if (lane == 0) s_fg[n][warp] = v;
    }
    __syncthreads();
    if (threadIdx.x < 8) {
        float s = 0.f;
#pragma unroll
        for (int wv = 0; wv < 8; wv++) s += s_fg[threadIdx.x][wv];
        g_fg_part[(b * 8 + threadIdx.x) * 256 + blk] = s;
    }
}

// ---------------------------------------------------------------- Lovász scan, fp32 (launch 4)
__global__ void __launch_bounds__(1024) k_scan() {
    int seg = blockIdx.x;
    int tid = threadIdx.x;
    int warp = tid >> 5, lane = tid & 31;
    __shared__ unsigned long long wsum[32];
    __shared__ float rs[32];

    float Pf = g_acc[seg * 6 + 0];          // exact integer < 2^20
    unsigned carry_p = 0, carry_n = 0;
    float lov = 0.0f;
    const unsigned long long* hp =
        reinterpret_cast<const unsigned long long*>(g_hist32) + (size_t)seg * NBINS;

    for (int it = 0; it < NBINS / 1024; it++) {
        int bin = NBINS - 1 - (it * 1024 + tid);
        unsigned long long pair = hp[bin];      // low=neg, high=pos
        unsigned nn = (unsigned)(pair & 0xffffffffu);
        unsigned np = (unsigned)(pair >> 32);
        unsigned long long inc = pair;
#pragma unroll
        for (int o = 1; o < 32; o <<= 1) {
            unsigned long long t = __shfl_up_sync(0xffffffffu, inc, o);
            if (lane >= o) inc += t;
        }
        if (lane == 31) wsum[warp] = inc;
        __syncthreads();
        if (warp == 0) {
            unsigned long long wv = wsum[lane];
#pragma unroll
            for (int o = 1; o < 32; o <<= 1) {
                unsigned long long t = __shfl_up_sync(0xffffffffu, wv, o);
                if (lane >= o) wv += t;
            }
            wsum[lane] = wv;
        }
        __syncthreads();
        unsigned long long incl = inc + (warp > 0 ? wsum[warp - 1] : 0ull);
        unsigned long long total = wsum[31];
        unsigned cp1 = carry_p + (unsigned)(incl >> 32);
        unsigned cn1 = carry_n + (unsigned)(incl & 0xffffffffu);
        unsigned cp0 = cp1 - np;
        unsigned cn0 = cn1 - nn;
        if (np | nn) {
            float j1 = 1.0f - __fdividef(Pf - (float)cp1, fmaxf(Pf + (float)cn1, 1.0f));
            float j0 = 1.0f - __fdividef(Pf - (float)cp0, fmaxf(Pf + (float)cn0, 1.0f));
            lov = fmaf(((float)bin + 0.5f) * (1.0f / BIN_SCALE), j1 - j0, lov);
        }
        carry_p += (unsigned)(total >> 32);
        carry_n += (unsigned)(total & 0xffffffffu);
        __syncthreads();
    }
    float lf = wred(lov);
    if (lane == 0) rs[warp] = lf;
    __syncthreads();
    if (tid < 32) {
        float v = wred(rs[tid]);
        if (tid == 0) g_lov[seg] = v;
    }
}

// ---------------------------------------------------------------- final (launch 5)
__global__ void __launch_bounds__(1024) k_final(const int* __restrict__ cls_ids,
                                                float* __restrict__ out) {
    __shared__ float s_fg[NSEG];
    __shared__ float s_bg[Bx];
    int warp = threadIdx.x >> 5, lane = threadIdx.x & 31;
    if (warp < NSEG) {
        float v = 0.f;
#pragma unroll
        for (int i = 0; i < 8; i++) v += g_fg_part[warp * 256 + lane + i * 32];
        v = wred(v);
        if (lane == 0) s_fg[warp] = v;
    } else if (warp < NSEG + Bx) {
        int b = warp - NSEG;
        float v = 0.f;
#pragma unroll
        for (int i = 0; i < 8; i++) v += g_bg_part[b * 256 + lane + i * 32];
        v = wred(v);
        if (lane == 0) s_bg[b] = v;
    }
    __syncthreads();
    if (threadIdx.x == 0) {
        float total = 0.f;
        for (int b = 0; b < Bx; b++) {
            float obj = 0.f, inst = 0.f, var = 0.f, fg = 0.f;
            for (int n = 0; n < 8; n++) {
                int seg = b * 8 + n;
                float cnt = g_acc[seg * 6 + 0];
                float valid = (cnt >= MINPIX) ? 1.f : 0.f;
                float cs = fmaxf(cnt, 1.f);
                float S0 = g_acc[seg * 6 + 3];
                float S1 = g_acc[seg * 6 + 4];
                float Q  = g_acc[seg * 6 + 5];
                float vi = (Q - (S0 * S0 + S1 * S1) / cs) / (2.f * cs);
                obj += valid;
                inst += g_lov[seg] * valid;
                var += vi * valid;
                fg += FGW[cls_ids[seg]] * s_fg[seg] * valid;
            }
            float os = fmaxf(obj, 1.f);
            float seed_l = (s_bg[b] + fg) * (1.0f / (float)HWx);
            total += inst / os + 10.f * (var / os) + seed_l;
        }
        out[0] = total * 0.5f;
    }
}

// ---------------------------------------------------------------- launch
extern "C" void kernel_launch(void* const* d_in, const int* in_sizes, int n_in,
                              void* d_out, int out_size) {
    const float* pred = (const float*)d_in[0];
    const int* bbox   = (const int*)d_in[1];
    const int* masks  = (const int*)d_in[2];
    const int* cls    = (const int*)d_in[3];
    (void)in_sizes; (void)n_in; (void)out_size;

    k_seed<<<Bx * BPB, 256>>>(pred, bbox);          // 0 (also zeroes hist)
    k_maskaccum<<<Bx * BPB, 256>>>(pred, masks);    // 1
    k_params<<<1, 1024>>>();                        // 2
    k_pass3<<<Bx * BPB, 256>>>(pred, cls);          // 3 <- profiled
    k_scan<<<NSEG, 1024>>>();                       // 4
    k_final<<<1, 1024>>>(cls, (float*)d_out);       // 5
}